// round 5
// baseline (speedup 1.0000x reference)
#include <cuda_runtime.h>
#include <cuda_bf16.h>
#include <stdint.h>

// ---------------------------------------------------------------------------
// MultiHeadSelfAttention: B=2, S=2048, D=1024, H=16, dk=64
// R4: projections write pre-split bf16 hi/lo planes; fused attention uses
//     cp.async double-buffered K/V; two-loop scheme (rowsum pass + normalized
//     write pass) eliminates the scale_rows kernel and 1 GB of attn traffic.
// ---------------------------------------------------------------------------

namespace {
constexpr int BATCH = 2, S = 2048, D = 1024, H = 16, DK = 64, BH = 32;
constexpr long long OUT_ELEMS = (long long)BATCH * S * D;          // 4,194,304
constexpr long long ATT_ELEMS = (long long)BH * S * (long long)S;  // 134,217,728
constexpr int QKST = 136;   // smem row stride in bf16: 64 hi + 64 lo + 8 pad
}

// Scratch (allocation-free): bf16 hi/lo planes for q,k,v + fp32 ctx
__device__ __nv_bfloat16 g_qh[(size_t)BH * S * DK];
__device__ __nv_bfloat16 g_ql[(size_t)BH * S * DK];
__device__ __nv_bfloat16 g_kh[(size_t)BH * S * DK];
__device__ __nv_bfloat16 g_kl[(size_t)BH * S * DK];
__device__ __nv_bfloat16 g_vh[(size_t)BH * S * DK];
__device__ __nv_bfloat16 g_vl[(size_t)BH * S * DK];
__device__ float g_ctx[(size_t)BATCH * S * D];

// ------------------------------ PTX helpers --------------------------------
__device__ __forceinline__ uint32_t smaddr(const void* p) {
    return (uint32_t)__cvta_generic_to_shared(p);
}
__device__ __forceinline__ void ldsm4(uint32_t& r0, uint32_t& r1, uint32_t& r2,
                                      uint32_t& r3, uint32_t a) {
    asm volatile("ldmatrix.sync.aligned.m8n8.x4.shared.b16 {%0,%1,%2,%3}, [%4];"
                 : "=r"(r0), "=r"(r1), "=r"(r2), "=r"(r3) : "r"(a));
}
__device__ __forceinline__ void ldsm4t(uint32_t& r0, uint32_t& r1, uint32_t& r2,
                                       uint32_t& r3, uint32_t a) {
    asm volatile("ldmatrix.sync.aligned.m8n8.x4.trans.shared.b16 {%0,%1,%2,%3}, [%4];"
                 : "=r"(r0), "=r"(r1), "=r"(r2), "=r"(r3) : "r"(a));
}
__device__ __forceinline__ void mma16816(float* c, const uint32_t* a,
                                         uint32_t b0, uint32_t b1) {
    asm volatile("mma.sync.aligned.m16n8k16.row.col.f32.bf16.bf16.f32 "
                 "{%0,%1,%2,%3}, {%4,%5,%6,%7}, {%8,%9}, {%0,%1,%2,%3};"
                 : "+f"(c[0]), "+f"(c[1]), "+f"(c[2]), "+f"(c[3])
                 : "r"(a[0]), "r"(a[1]), "r"(a[2]), "r"(a[3]), "r"(b0), "r"(b1));
}
__device__ __forceinline__ uint32_t packbf(float a, float b) {
    __nv_bfloat162 t = __halves2bfloat162(__float2bfloat16(a), __float2bfloat16(b));
    return *reinterpret_cast<uint32_t*>(&t);
}
__device__ __forceinline__ void cpa16(uint32_t dst, const void* src) {
    asm volatile("cp.async.cg.shared.global [%0], [%1], 16;" :: "r"(dst), "l"(src));
}
#define CP_COMMIT() asm volatile("cp.async.commit_group;")
#define CP_WAIT(N)  asm volatile("cp.async.wait_group %0;" :: "n"(N))

// fp32 float4 -> (4x bf16 hi, 4x bf16 lo) packed as uint2 each
__device__ __forceinline__ void split4(const float4 f, uint2& hi, uint2& lo) {
    __nv_bfloat16 hx = __float2bfloat16(f.x), hy = __float2bfloat16(f.y);
    __nv_bfloat16 hz = __float2bfloat16(f.z), hw = __float2bfloat16(f.w);
    __nv_bfloat16 lx = __float2bfloat16(f.x - __bfloat162float(hx));
    __nv_bfloat16 ly = __float2bfloat16(f.y - __bfloat162float(hy));
    __nv_bfloat16 lz = __float2bfloat16(f.z - __bfloat162float(hz));
    __nv_bfloat16 lw = __float2bfloat16(f.w - __bfloat162float(hw));
    __nv_bfloat162 h01 = __halves2bfloat162(hx, hy), h23 = __halves2bfloat162(hz, hw);
    __nv_bfloat162 l01 = __halves2bfloat162(lx, ly), l23 = __halves2bfloat162(lz, lw);
    hi.x = *reinterpret_cast<uint32_t*>(&h01); hi.y = *reinterpret_cast<uint32_t*>(&h23);
    lo.x = *reinterpret_cast<uint32_t*>(&l01); lo.y = *reinterpret_cast<uint32_t*>(&l23);
}

// ---------------------------------------------------------------------------
// Shared SGEMM-on-mma mainloop (NT, 128x128 CTA, BK=16, bf16 hi/lo split).
// EPI=0: fp32 C (row-major). EPI=1: bf16 hi/lo planes in [B,H,S,DK] layout.
// ---------------------------------------------------------------------------
template <int EPI>
__global__ void __launch_bounds__(256)
gemm_nt_mma(const float* __restrict__ A, const float* __restrict__ Bw,
            float* __restrict__ C, __nv_bfloat16* __restrict__ Chi,
            __nv_bfloat16* __restrict__ Clo, int K, int N, float alpha)
{
    constexpr int ST = 40;
    __shared__ __align__(16) __nv_bfloat16 Asm[2][128][ST];
    __shared__ __align__(16) __nv_bfloat16 Bsm[2][128][ST];

    const int tid = threadIdx.x, w = tid >> 5, l = tid & 31;
    const int m0 = blockIdx.y * 128, n0 = blockIdx.x * 128;
    const int wm = (w >> 2) * 64, wn = (w & 3) * 32;

    const int lr = l & 7;
    const int kc = (l >> 3) * 4;
    const int r0l = w * 16 + lr, r1l = r0l + 8;

    const int afr = wm + (l & 15);
    const int afc = (l >> 4) * 8;
    const int bg  = l >> 3;
    const int bfr = wn + ((bg >> 1) << 3) + (l & 7);
    const int bfc = (bg & 1) * 8;

    float4 aR0, aR1, bR0, bR1;
    float acc[4][4][4] = {};

    auto loadG = [&](int kt) {
        const size_t ko = (size_t)kt * 16 + kc;
        aR0 = *(const float4*)(A + (size_t)(m0 + r0l) * K + ko);
        aR1 = *(const float4*)(A + (size_t)(m0 + r1l) * K + ko);
        bR0 = *(const float4*)(Bw + (size_t)(n0 + r0l) * K + ko);
        bR1 = *(const float4*)(Bw + (size_t)(n0 + r1l) * K + ko);
    };
    auto storeS = [&](int buf) {
        uint2 hi, lo;
        split4(aR0, hi, lo);
        *(uint2*)&Asm[buf][r0l][kc] = hi; *(uint2*)&Asm[buf][r0l][16 + kc] = lo;
        split4(aR1, hi, lo);
        *(uint2*)&Asm[buf][r1l][kc] = hi; *(uint2*)&Asm[buf][r1l][16 + kc] = lo;
        split4(bR0, hi, lo);
        *(uint2*)&Bsm[buf][r0l][kc] = hi; *(uint2*)&Bsm[buf][r0l][16 + kc] = lo;
        split4(bR1, hi, lo);
        *(uint2*)&Bsm[buf][r1l][kc] = hi; *(uint2*)&Bsm[buf][r1l][16 + kc] = lo;
    };

    loadG(0); storeS(0); __syncthreads();
    const int KT = K / 16;
    int buf = 0;
    for (int kt = 0; kt < KT; kt++) {
        const bool more = (kt + 1 < KT);
        if (more) loadG(kt + 1);

        uint32_t Bh[8], Bl[8];
        ldsm4(Bh[0], Bh[1], Bh[2], Bh[3], smaddr(&Bsm[buf][bfr][bfc]));
        ldsm4(Bh[4], Bh[5], Bh[6], Bh[7], smaddr(&Bsm[buf][bfr + 16][bfc]));
        ldsm4(Bl[0], Bl[1], Bl[2], Bl[3], smaddr(&Bsm[buf][bfr][bfc + 16]));
        ldsm4(Bl[4], Bl[5], Bl[6], Bl[7], smaddr(&Bsm[buf][bfr + 16][bfc + 16]));

        #pragma unroll
        for (int mf = 0; mf < 4; mf++) {
            uint32_t Ah[4], Al[4];
            ldsm4(Ah[0], Ah[1], Ah[2], Ah[3], smaddr(&Asm[buf][afr + mf * 16][afc]));
            ldsm4(Al[0], Al[1], Al[2], Al[3], smaddr(&Asm[buf][afr + mf * 16][afc + 16]));
            #pragma unroll
            for (int nf = 0; nf < 4; nf++) {
                float* c = acc[mf][nf];
                mma16816(c, Ah, Bh[nf * 2], Bh[nf * 2 + 1]);
                mma16816(c, Ah, Bl[nf * 2], Bl[nf * 2 + 1]);
                mma16816(c, Al, Bh[nf * 2], Bh[nf * 2 + 1]);
            }
        }
        if (more) { buf ^= 1; storeS(buf); __syncthreads(); }
    }

    const int er = l >> 2, ec = (l & 3) * 2;
    #pragma unroll
    for (int mf = 0; mf < 4; mf++) {
        #pragma unroll
        for (int nf = 0; nf < 4; nf++) {
            const float* c = acc[mf][nf];
            const int rr = m0 + wm + mf * 16 + er;
            const int cc = n0 + wn + nf * 8 + ec;
            if (EPI == 1) {
                // [B*S, D] -> bf16 hi/lo planes, head-major [B,H,S,DK]
                const int hh = cc >> 6, dd = cc & 63;
                const int bb = rr >> 11, ss = rr & (S - 1);
                const int rr2 = rr + 8, bb2 = rr2 >> 11, ss2 = rr2 & (S - 1);
                const size_t i0 = (((size_t)bb  * H + hh) * S + ss)  * DK + dd;
                const size_t i1 = (((size_t)bb2 * H + hh) * S + ss2) * DK + dd;
                __nv_bfloat16 h0 = __float2bfloat16(c[0]), h1 = __float2bfloat16(c[1]);
                __nv_bfloat16 h2 = __float2bfloat16(c[2]), h3 = __float2bfloat16(c[3]);
                *(uint32_t*)&Chi[i0] = packbf(__bfloat162float(h0), __bfloat162float(h1));
                *(uint32_t*)&Clo[i0] = packbf(c[0] - __bfloat162float(h0),
                                              c[1] - __bfloat162float(h1));
                *(uint32_t*)&Chi[i1] = packbf(__bfloat162float(h2), __bfloat162float(h3));
                *(uint32_t*)&Clo[i1] = packbf(c[2] - __bfloat162float(h2),
                                              c[3] - __bfloat162float(h3));
            } else {
                *(float2*)&C[(size_t)rr * N + cc] =
                    make_float2(c[0] * alpha, c[1] * alpha);
                *(float2*)&C[(size_t)(rr + 8) * N + cc] =
                    make_float2(c[2] * alpha, c[3] * alpha);
            }
        }
    }
}

// ---------------------------------------------------------------------------
// Fused attention, two-loop. Grid (S/128, BH), 256 thr / 8 warps.
// Warp S-tile: 32(m) x 64(n). Loop1: QK+exp -> rowsums. Loop2: QK+exp
// normalized -> write attn (if WRITE_E), P@V -> ctx.
// K/V tiles double-buffered via cp.async from pre-split bf16 planes.
// ---------------------------------------------------------------------------
template <bool WRITE_E>
__global__ void __launch_bounds__(256)
fused_attn(const __nv_bfloat16* __restrict__ Qh, const __nv_bfloat16* __restrict__ Ql,
           const __nv_bfloat16* __restrict__ Kh, const __nv_bfloat16* __restrict__ Kl,
           const __nv_bfloat16* __restrict__ Vh, const __nv_bfloat16* __restrict__ Vl,
           float* __restrict__ ctx, float* __restrict__ attn)
{
    extern __shared__ __align__(16) char sm[];
    __nv_bfloat16* Qs  = (__nv_bfloat16*)sm;         // [128][136]
    __nv_bfloat16* Kb[2] = { Qs + 128 * QKST, Qs + 2 * 128 * QKST };
    __nv_bfloat16* Vb[2] = { Qs + 3 * 128 * QKST, Qs + 4 * 128 * QKST };
    float* rsm  = (float*)(Qs + 5 * 128 * QKST);     // [128]
    float* rbuf = (float*)Kb[0];                     // reused after loops

    const int z = blockIdx.y, y0 = blockIdx.x * 128;
    const int bz = z >> 4, hz = z & 15;
    const size_t zb = (size_t)z * S * DK;

    const int tid = threadIdx.x, w = tid >> 5, l = tid & 31;
    const int wm = (w >> 1) * 32, wn = (w & 1) * 64;

    // cp.async mapping: thread covers one full 128B row-plane (8 x 16B)
    const int crow = tid >> 1, cpl = tid & 1;

    // fragment index helpers (as R3)
    const int afr = (l & 15), afc = (l >> 4) * 8;
    const int bg = l >> 3, bRow = ((bg >> 1) << 3) + (l & 7), bc8 = (bg & 1) * 8;
    const int vkr = ((l >> 3) & 1) * 8 + (l & 7), vnc = (l >> 4) * 8;

    auto issue = [&](const __nv_bfloat16* hi, const __nv_bfloat16* lo,
                     int row0, __nv_bfloat16* dst) {
        const __nv_bfloat16* s = (cpl ? lo : hi) + zb + (size_t)(row0 + crow) * DK;
        const uint32_t d = smaddr(dst + crow * QKST + cpl * 64);
        #pragma unroll
        for (int i = 0; i < 8; i++) cpa16(d + i * 16, s + i * 8);
    };

    auto computeQK = [&](const __nv_bfloat16* Ks, float (&Sc)[2][8][4]) {
        #pragma unroll
        for (int kk = 0; kk < 4; kk++) {
            uint32_t Ah[2][4], Al[2][4];
            #pragma unroll
            for (int mf = 0; mf < 2; mf++) {
                const int row = wm + mf * 16 + afr;
                ldsm4(Ah[mf][0], Ah[mf][1], Ah[mf][2], Ah[mf][3],
                      smaddr(&Qs[row * QKST + kk * 16 + afc]));
                ldsm4(Al[mf][0], Al[mf][1], Al[mf][2], Al[mf][3],
                      smaddr(&Qs[row * QKST + 64 + kk * 16 + afc]));
            }
            #pragma unroll
            for (int g = 0; g < 4; g++) {
                uint32_t Bh[4], Bl[4];
                const int row = wn + g * 16 + bRow;
                ldsm4(Bh[0], Bh[1], Bh[2], Bh[3],
                      smaddr(&Ks[row * QKST + kk * 16 + bc8]));
                ldsm4(Bl[0], Bl[1], Bl[2], Bl[3],
                      smaddr(&Ks[row * QKST + 64 + kk * 16 + bc8]));
                #pragma unroll
                for (int mf = 0; mf < 2; mf++) {
                    #pragma unroll
                    for (int sub = 0; sub < 2; sub++) {
                        float* c = Sc[mf][2 * g + sub];
                        mma16816(c, Ah[mf], Bh[2 * sub], Bh[2 * sub + 1]);
                        mma16816(c, Ah[mf], Bl[2 * sub], Bl[2 * sub + 1]);
                        mma16816(c, Al[mf], Bh[2 * sub], Bh[2 * sub + 1]);
                    }
                }
            }
        }
    };

    if (tid < 128) rsm[tid] = 0.0f;
    issue(Qh, Ql, y0, Qs);
    issue(Kh, Kl, 0, Kb[0]);
    CP_COMMIT();

    float rp[2][2] = {};

    if (WRITE_E) {
        // ---- loop 1: rowsums only ----
        for (int kt = 0; kt < 16; kt++) {
            if (kt < 15) issue(Kh, Kl, (kt + 1) * 128, Kb[(kt + 1) & 1]);
            CP_COMMIT();
            CP_WAIT(1); __syncthreads();
            float Sacc[2][8][4] = {};
            computeQK(Kb[kt & 1], Sacc);
            #pragma unroll
            for (int mf = 0; mf < 2; mf++)
                #pragma unroll
                for (int nf = 0; nf < 8; nf++) {
                    float* c = Sacc[mf][nf];
                    rp[mf][0] += __expf(c[0] * 0.125f) + __expf(c[1] * 0.125f);
                    rp[mf][1] += __expf(c[2] * 0.125f) + __expf(c[3] * 0.125f);
                }
            __syncthreads();
        }
        #pragma unroll
        for (int mf = 0; mf < 2; mf++)
            #pragma unroll
            for (int rh = 0; rh < 2; rh++) {
                float v = rp[mf][rh];
                v += __shfl_xor_sync(0xffffffffu, v, 1);
                v += __shfl_xor_sync(0xffffffffu, v, 2);
                if ((l & 3) == 0)
                    atomicAdd(&rsm[wm + mf * 16 + (l >> 2) + rh * 8], v);
            }
        __syncthreads();
        if (tid < 128) rsm[tid] = 1.0f / rsm[tid];
        __syncthreads();
    }

    float inv[2][2] = {{1.f, 1.f}, {1.f, 1.f}};
    if (WRITE_E) {
        inv[0][0] = rsm[wm + (l >> 2)];      inv[0][1] = rsm[wm + (l >> 2) + 8];
        inv[1][0] = rsm[wm + 16 + (l >> 2)]; inv[1][1] = rsm[wm + 16 + (l >> 2) + 8];
    }

    // ---- loop 2: attn write (normalized) + P@V ----
    float acc[2][8][4] = {};
    issue(Kh, Kl, 0, Kb[0]);
    issue(Vh, Vl, 0, Vb[0]);
    CP_COMMIT();
    for (int kt = 0; kt < 16; kt++) {
        if (kt < 15) {
            issue(Kh, Kl, (kt + 1) * 128, Kb[(kt + 1) & 1]);
            issue(Vh, Vl, (kt + 1) * 128, Vb[(kt + 1) & 1]);
        }
        CP_COMMIT();
        CP_WAIT(1); __syncthreads();
        const __nv_bfloat16* Ks = Kb[kt & 1];
        const __nv_bfloat16* Vs = Vb[kt & 1];

        float Sacc[2][8][4] = {};
        computeQK(Ks, Sacc);

        uint32_t PA0[2][8], PA1[2][8], PL0[2][8], PL1[2][8];
        #pragma unroll
        for (int mf = 0; mf < 2; mf++) {
            #pragma unroll
            for (int nf = 0; nf < 8; nf++) {
                float* c = Sacc[mf][nf];
                float e0 = __expf(c[0] * 0.125f), e1 = __expf(c[1] * 0.125f);
                float e2 = __expf(c[2] * 0.125f), e3 = __expf(c[3] * 0.125f);
                if (WRITE_E) {
                    e0 *= inv[mf][0]; e1 *= inv[mf][0];
                    e2 *= inv[mf][1]; e3 *= inv[mf][1];
                } else {
                    rp[mf][0] += e0 + e1;
                    rp[mf][1] += e2 + e3;
                }
                __nv_bfloat16 h0 = __float2bfloat16(e0), h1 = __float2bfloat16(e1);
                __nv_bfloat16 h2 = __float2bfloat16(e2), h3 = __float2bfloat16(e3);
                PA0[mf][nf] = packbf(__bfloat162float(h0), __bfloat162float(h1));
                PA1[mf][nf] = packbf(__bfloat162float(h2), __bfloat162float(h3));
                PL0[mf][nf] = packbf(e0 - __bfloat162float(h0), e1 - __bfloat162float(h1));
                PL1[mf][nf] = packbf(e2 - __bfloat162float(h2), e3 - __bfloat162float(h3));
                if (WRITE_E) {
                    const int grow = y0 + wm + mf * 16 + (l >> 2);
                    const int gcol = kt * 128 + wn + nf * 8 + 2 * (l & 3);
                    *(float2*)&attn[((size_t)z * S + grow) * S + gcol] = make_float2(e0, e1);
                    *(float2*)&attn[((size_t)z * S + grow + 8) * S + gcol] = make_float2(e2, e3);
                }
            }
        }

        #pragma unroll
        for (int j = 0; j < 4; j++) {
            uint32_t Aph[2][4], Apl[2][4];
            #pragma unroll
            for (int mf = 0; mf < 2; mf++) {
                Aph[mf][0] = PA0[mf][2 * j];     Aph[mf][1] = PA1[mf][2 * j];
                Aph[mf][2] = PA0[mf][2 * j + 1]; Aph[mf][3] = PA1[mf][2 * j + 1];
                Apl[mf][0] = PL0[mf][2 * j];     Apl[mf][1] = PL1[mf][2 * j];
                Apl[mf][2] = PL0[mf][2 * j + 1]; Apl[mf][3] = PL1[mf][2 * j + 1];
            }
            #pragma unroll
            for (int g = 0; g < 4; g++) {
                uint32_t Vhf[4], Vlf[4];
                const int row = wn + j * 16 + vkr;
                ldsm4t(Vhf[0], Vhf[1], Vhf[2], Vhf[3],
                       smaddr(&Vs[row * QKST + g * 16 + vnc]));
                ldsm4t(Vlf[0], Vlf[1], Vlf[2], Vlf[3],
                       smaddr(&Vs[row * QKST + 64 + g * 16 + vnc]));
                #pragma unroll
                for (int mf = 0; mf < 2; mf++) {
                    #pragma unroll
                    for (int sub = 0; sub < 2; sub++) {
                        float* c = acc[mf][2 * g + sub];
                        mma16816(c, Aph[mf], Vhf[2 * sub], Vhf[2 * sub + 1]);
                        mma16816(c, Aph[mf], Vlf[2 * sub], Vlf[2 * sub + 1]);
                        mma16816(c, Apl[mf], Vhf[2 * sub], Vhf[2 * sub + 1]);
                    }
                }
            }
        }
        __syncthreads();
    }

    if (!WRITE_E) {
        #pragma unroll
        for (int mf = 0; mf < 2; mf++)
            #pragma unroll
            for (int rh = 0; rh < 2; rh++) {
                float v = rp[mf][rh];
                v += __shfl_xor_sync(0xffffffffu, v, 1);
                v += __shfl_xor_sync(0xffffffffu, v, 2);
                if ((l & 3) == 0)
                    atomicAdd(&rsm[wm + mf * 16 + (l >> 2) + rh * 8], v);
            }
        __syncthreads();
        if (tid < 128) rsm[tid] = 1.0f / rsm[tid];
        __syncthreads();
    }

    // ---- pair-reduce ctx across the two n-half warps, store ----
    if (w & 1) {
        #pragma unroll
        for (int mf = 0; mf < 2; mf++)
            #pragma unroll
            for (int nf = 0; nf < 8; nf++) {
                const int r = wm + mf * 16 + (l >> 2);
                const int c = nf * 8 + 2 * (l & 3);
                *(float2*)&rbuf[r * 66 + c] = make_float2(acc[mf][nf][0], acc[mf][nf][1]);
                *(float2*)&rbuf[(r + 8) * 66 + c] = make_float2(acc[mf][nf][2], acc[mf][nf][3]);
            }
    }
    __syncthreads();
    if (!(w & 1)) {
        #pragma unroll
        for (int mf = 0; mf < 2; mf++) {
            const int r = wm + mf * 16 + (l >> 2);
            const float s0 = WRITE_E ? 1.0f : rsm[r];
            const float s1 = WRITE_E ? 1.0f : rsm[r + 8];
            #pragma unroll
            for (int nf = 0; nf < 8; nf++) {
                const int c = nf * 8 + 2 * (l & 3);
                float2 p0 = *(float2*)&rbuf[r * 66 + c];
                float2 p1 = *(float2*)&rbuf[(r + 8) * 66 + c];
                *(float2*)&ctx[((size_t)bz * S + y0 + r) * D + hz * 64 + c] =
                    make_float2((acc[mf][nf][0] + p0.x) * s0, (acc[mf][nf][1] + p0.y) * s0);
                *(float2*)&ctx[((size_t)bz * S + y0 + r + 8) * D + hz * 64 + c] =
                    make_float2((acc[mf][nf][2] + p1.x) * s1, (acc[mf][nf][3] + p1.y) * s1);
            }
        }
    }
}

// ---------------------------------------------------------------------------
extern "C" void kernel_launch(void* const* d_in, const int* in_sizes, int n_in,
                              void* d_out, int out_size)
{
    const float* query = (const float*)d_in[0];
    const float* key_i = (const float*)d_in[1];
    const float* value = (const float*)d_in[2];
    const float* w_q   = (const float*)d_in[3];
    const float* w_k   = (const float*)d_in[4];
    const float* w_v   = (const float*)d_in[5];
    const float* w_o   = (const float*)d_in[6];
    float* out = (float*)d_out;

    __nv_bfloat16 *qh, *ql, *kh, *kl, *vh, *vl;
    float *cp;
    cudaGetSymbolAddress((void**)&qh, g_qh);
    cudaGetSymbolAddress((void**)&ql, g_ql);
    cudaGetSymbolAddress((void**)&kh, g_kh);
    cudaGetSymbolAddress((void**)&kl, g_kl);
    cudaGetSymbolAddress((void**)&vh, g_vh);
    cudaGetSymbolAddress((void**)&vl, g_vl);
    cudaGetSymbolAddress((void**)&cp, g_ctx);

    const bool want_attn = ((long long)out_size >= OUT_ELEMS + ATT_ELEMS);
    float* attn = want_attn ? (out + OUT_ELEMS) : nullptr;

    const dim3 tb(256);
    const dim3 gproj(D / 128, (BATCH * S) / 128, 1);

    // q/k/v projections -> bf16 hi/lo planes, head-major [B,H,S,DK]
    gemm_nt_mma<1><<<gproj, tb>>>(query, w_q, nullptr, qh, ql, D, D, 1.0f);
    gemm_nt_mma<1><<<gproj, tb>>>(key_i, w_k, nullptr, kh, kl, D, D, 1.0f);
    gemm_nt_mma<1><<<gproj, tb>>>(value, w_v, nullptr, vh, vl, D, D, 1.0f);

    // fused attention
    const int smem = 5 * 128 * QKST * 2 + 128 * 4;   // 174592 B
    const dim3 gf(S / 128, BH);
    if (want_attn) {
        cudaFuncSetAttribute(fused_attn<true>,
                             cudaFuncAttributeMaxDynamicSharedMemorySize, smem);
        fused_attn<true><<<gf, tb, smem>>>(qh, ql, kh, kl, vh, vl, cp, attn);
    } else {
        cudaFuncSetAttribute(fused_attn<false>,
                             cudaFuncAttributeMaxDynamicSharedMemorySize, smem);
        fused_attn<false><<<gf, tb, smem>>>(qh, ql, kh, kl, vh, vl, cp, nullptr);
    }

    // out = ctx @ Wo^T
    gemm_nt_mma<0><<<gproj, tb>>>(cp, w_o, out, nullptr, nullptr, D, D, 1.0f);
}

// round 6
// speedup vs baseline: 1.0877x; 1.0877x over previous
#include <cuda_runtime.h>
#include <cuda_bf16.h>
#include <stdint.h>

// ---------------------------------------------------------------------------
// MultiHeadSelfAttention: B=2, S=2048, D=1024, H=16, dk=64
// R5: two-loop fused attention, pass1 = cheap bf16-only rowsums (1 mma/step,
//     K-hi loads only, double-buffered), pass2 = full hi/lo precision.
//     64-row Q tiles + reg cap 128 + 87KB smem -> 2 CTAs/SM (16 warps).
// ---------------------------------------------------------------------------

namespace {
constexpr int BATCH = 2, S = 2048, D = 1024, H = 16, DK = 64, BH = 32;
constexpr long long OUT_ELEMS = (long long)BATCH * S * D;          // 4,194,304
constexpr long long ATT_ELEMS = (long long)BH * S * (long long)S;  // 134,217,728
constexpr int QKST = 136;   // smem row stride in bf16: 64 hi + 64 lo + 8 pad
}

// Scratch (allocation-free): bf16 hi/lo planes for q,k,v + fp32 ctx
__device__ __nv_bfloat16 g_qh[(size_t)BH * S * DK];
__device__ __nv_bfloat16 g_ql[(size_t)BH * S * DK];
__device__ __nv_bfloat16 g_kh[(size_t)BH * S * DK];
__device__ __nv_bfloat16 g_kl[(size_t)BH * S * DK];
__device__ __nv_bfloat16 g_vh[(size_t)BH * S * DK];
__device__ __nv_bfloat16 g_vl[(size_t)BH * S * DK];
__device__ float g_ctx[(size_t)BATCH * S * D];

// ------------------------------ PTX helpers --------------------------------
__device__ __forceinline__ uint32_t smaddr(const void* p) {
    return (uint32_t)__cvta_generic_to_shared(p);
}
__device__ __forceinline__ void ldsm4(uint32_t& r0, uint32_t& r1, uint32_t& r2,
                                      uint32_t& r3, uint32_t a) {
    asm volatile("ldmatrix.sync.aligned.m8n8.x4.shared.b16 {%0,%1,%2,%3}, [%4];"
                 : "=r"(r0), "=r"(r1), "=r"(r2), "=r"(r3) : "r"(a));
}
__device__ __forceinline__ void ldsm4t(uint32_t& r0, uint32_t& r1, uint32_t& r2,
                                       uint32_t& r3, uint32_t a) {
    asm volatile("ldmatrix.sync.aligned.m8n8.x4.trans.shared.b16 {%0,%1,%2,%3}, [%4];"
                 : "=r"(r0), "=r"(r1), "=r"(r2), "=r"(r3) : "r"(a));
}
__device__ __forceinline__ void mma16816(float* c, const uint32_t* a,
                                         uint32_t b0, uint32_t b1) {
    asm volatile("mma.sync.aligned.m16n8k16.row.col.f32.bf16.bf16.f32 "
                 "{%0,%1,%2,%3}, {%4,%5,%6,%7}, {%8,%9}, {%0,%1,%2,%3};"
                 : "+f"(c[0]), "+f"(c[1]), "+f"(c[2]), "+f"(c[3])
                 : "r"(a[0]), "r"(a[1]), "r"(a[2]), "r"(a[3]), "r"(b0), "r"(b1));
}
__device__ __forceinline__ uint32_t packbf(float a, float b) {
    __nv_bfloat162 t = __halves2bfloat162(__float2bfloat16(a), __float2bfloat16(b));
    return *reinterpret_cast<uint32_t*>(&t);
}
__device__ __forceinline__ void cpa16(uint32_t dst, const void* src) {
    asm volatile("cp.async.cg.shared.global [%0], [%1], 16;" :: "r"(dst), "l"(src));
}
#define CP_COMMIT() asm volatile("cp.async.commit_group;")
#define CP_WAIT(N)  asm volatile("cp.async.wait_group %0;" :: "n"(N))

// fp32 float4 -> (4x bf16 hi, 4x bf16 lo) packed as uint2 each
__device__ __forceinline__ void split4(const float4 f, uint2& hi, uint2& lo) {
    __nv_bfloat16 hx = __float2bfloat16(f.x), hy = __float2bfloat16(f.y);
    __nv_bfloat16 hz = __float2bfloat16(f.z), hw = __float2bfloat16(f.w);
    __nv_bfloat16 lx = __float2bfloat16(f.x - __bfloat162float(hx));
    __nv_bfloat16 ly = __float2bfloat16(f.y - __bfloat162float(hy));
    __nv_bfloat16 lz = __float2bfloat16(f.z - __bfloat162float(hz));
    __nv_bfloat16 lw = __float2bfloat16(f.w - __bfloat162float(hw));
    __nv_bfloat162 h01 = __halves2bfloat162(hx, hy), h23 = __halves2bfloat162(hz, hw);
    __nv_bfloat162 l01 = __halves2bfloat162(lx, ly), l23 = __halves2bfloat162(lz, lw);
    hi.x = *reinterpret_cast<uint32_t*>(&h01); hi.y = *reinterpret_cast<uint32_t*>(&h23);
    lo.x = *reinterpret_cast<uint32_t*>(&l01); lo.y = *reinterpret_cast<uint32_t*>(&l23);
}

// ---------------------------------------------------------------------------
// Dense SGEMM-on-mma (NT, 128x128 CTA, BK=16, hi/lo split) - as R4.
// EPI=0: fp32 C row-major. EPI=1: bf16 hi/lo planes, head-major [B,H,S,DK].
// ---------------------------------------------------------------------------
template <int EPI>
__global__ void __launch_bounds__(256)
gemm_nt_mma(const float* __restrict__ A, const float* __restrict__ Bw,
            float* __restrict__ C, __nv_bfloat16* __restrict__ Chi,
            __nv_bfloat16* __restrict__ Clo, int K, int N, float alpha)
{
    constexpr int ST = 40;
    __shared__ __align__(16) __nv_bfloat16 Asm[2][128][ST];
    __shared__ __align__(16) __nv_bfloat16 Bsm[2][128][ST];

    const int tid = threadIdx.x, w = tid >> 5, l = tid & 31;
    const int m0 = blockIdx.y * 128, n0 = blockIdx.x * 128;
    const int wm = (w >> 2) * 64, wn = (w & 3) * 32;

    const int lr = l & 7;
    const int kc = (l >> 3) * 4;
    const int r0l = w * 16 + lr, r1l = r0l + 8;

    const int afr = wm + (l & 15);
    const int afc = (l >> 4) * 8;
    const int bg  = l >> 3;
    const int bfr = wn + ((bg >> 1) << 3) + (l & 7);
    const int bfc = (bg & 1) * 8;

    float4 aR0, aR1, bR0, bR1;
    float acc[4][4][4] = {};

    auto loadG = [&](int kt) {
        const size_t ko = (size_t)kt * 16 + kc;
        aR0 = *(const float4*)(A + (size_t)(m0 + r0l) * K + ko);
        aR1 = *(const float4*)(A + (size_t)(m0 + r1l) * K + ko);
        bR0 = *(const float4*)(Bw + (size_t)(n0 + r0l) * K + ko);
        bR1 = *(const float4*)(Bw + (size_t)(n0 + r1l) * K + ko);
    };
    auto storeS = [&](int buf) {
        uint2 hi, lo;
        split4(aR0, hi, lo);
        *(uint2*)&Asm[buf][r0l][kc] = hi; *(uint2*)&Asm[buf][r0l][16 + kc] = lo;
        split4(aR1, hi, lo);
        *(uint2*)&Asm[buf][r1l][kc] = hi; *(uint2*)&Asm[buf][r1l][16 + kc] = lo;
        split4(bR0, hi, lo);
        *(uint2*)&Bsm[buf][r0l][kc] = hi; *(uint2*)&Bsm[buf][r0l][16 + kc] = lo;
        split4(bR1, hi, lo);
        *(uint2*)&Bsm[buf][r1l][kc] = hi; *(uint2*)&Bsm[buf][r1l][16 + kc] = lo;
    };

    loadG(0); storeS(0); __syncthreads();
    const int KT = K / 16;
    int buf = 0;
    for (int kt = 0; kt < KT; kt++) {
        const bool more = (kt + 1 < KT);
        if (more) loadG(kt + 1);

        uint32_t Bh[8], Bl[8];
        ldsm4(Bh[0], Bh[1], Bh[2], Bh[3], smaddr(&Bsm[buf][bfr][bfc]));
        ldsm4(Bh[4], Bh[5], Bh[6], Bh[7], smaddr(&Bsm[buf][bfr + 16][bfc]));
        ldsm4(Bl[0], Bl[1], Bl[2], Bl[3], smaddr(&Bsm[buf][bfr][bfc + 16]));
        ldsm4(Bl[4], Bl[5], Bl[6], Bl[7], smaddr(&Bsm[buf][bfr + 16][bfc + 16]));

        #pragma unroll
        for (int mf = 0; mf < 4; mf++) {
            uint32_t Ah[4], Al[4];
            ldsm4(Ah[0], Ah[1], Ah[2], Ah[3], smaddr(&Asm[buf][afr + mf * 16][afc]));
            ldsm4(Al[0], Al[1], Al[2], Al[3], smaddr(&Asm[buf][afr + mf * 16][afc + 16]));
            #pragma unroll
            for (int nf = 0; nf < 4; nf++) {
                float* c = acc[mf][nf];
                mma16816(c, Ah, Bh[nf * 2], Bh[nf * 2 + 1]);
                mma16816(c, Ah, Bl[nf * 2], Bl[nf * 2 + 1]);
                mma16816(c, Al, Bh[nf * 2], Bh[nf * 2 + 1]);
            }
        }
        if (more) { buf ^= 1; storeS(buf); __syncthreads(); }
    }

    const int er = l >> 2, ec = (l & 3) * 2;
    #pragma unroll
    for (int mf = 0; mf < 4; mf++) {
        #pragma unroll
        for (int nf = 0; nf < 4; nf++) {
            const float* c = acc[mf][nf];
            const int rr = m0 + wm + mf * 16 + er;
            const int cc = n0 + wn + nf * 8 + ec;
            if (EPI == 1) {
                const int hh = cc >> 6, dd = cc & 63;
                const int bb = rr >> 11, ss = rr & (S - 1);
                const int rr2 = rr + 8, bb2 = rr2 >> 11, ss2 = rr2 & (S - 1);
                const size_t i0 = (((size_t)bb  * H + hh) * S + ss)  * DK + dd;
                const size_t i1 = (((size_t)bb2 * H + hh) * S + ss2) * DK + dd;
                __nv_bfloat16 h0 = __float2bfloat16(c[0]), h1 = __float2bfloat16(c[1]);
                __nv_bfloat16 h2 = __float2bfloat16(c[2]), h3 = __float2bfloat16(c[3]);
                *(uint32_t*)&Chi[i0] = packbf(__bfloat162float(h0), __bfloat162float(h1));
                *(uint32_t*)&Clo[i0] = packbf(c[0] - __bfloat162float(h0),
                                              c[1] - __bfloat162float(h1));
                *(uint32_t*)&Chi[i1] = packbf(__bfloat162float(h2), __bfloat162float(h3));
                *(uint32_t*)&Clo[i1] = packbf(c[2] - __bfloat162float(h2),
                                              c[3] - __bfloat162float(h3));
            } else {
                *(float2*)&C[(size_t)rr * N + cc] =
                    make_float2(c[0] * alpha, c[1] * alpha);
                *(float2*)&C[(size_t)(rr + 8) * N + cc] =
                    make_float2(c[2] * alpha, c[3] * alpha);
            }
        }
    }
}

// ---------------------------------------------------------------------------
// Fused attention. Grid (S/64, BH); 256 thr / 8 warps; 2 CTAs/SM.
// CTA tile: 64 Q-rows x 128 K-cols per step. Warp: 16(m) x 64(n k-half).
// WRITE_E: pass1 bf16-only rowsums, pass2 writes normalized attn + P@V.
// ---------------------------------------------------------------------------
template <bool WRITE_E>
__global__ void __launch_bounds__(256, 2)
fused_attn(const __nv_bfloat16* __restrict__ Qh, const __nv_bfloat16* __restrict__ Ql,
           const __nv_bfloat16* __restrict__ Kh, const __nv_bfloat16* __restrict__ Kl,
           const __nv_bfloat16* __restrict__ Vh, const __nv_bfloat16* __restrict__ Vl,
           float* __restrict__ ctx, float* __restrict__ attn)
{
    extern __shared__ __align__(16) char sm[];
    __nv_bfloat16* Qs = (__nv_bfloat16*)sm;          // [64][136]
    __nv_bfloat16* Ks = Qs + 64 * QKST;              // [128][136]
    __nv_bfloat16* Vs = Ks + 128 * QKST;             // [128][136]
    float* rsm  = (float*)(Vs + 128 * QKST);         // [64]
    float* rbuf = (float*)Ks;                        // reused in epilogue

    const int z = blockIdx.y, y0 = blockIdx.x * 64;
    const int bz = z >> 4, hz = z & 15;
    const size_t zb = (size_t)z * S * DK;

    const int tid = threadIdx.x, w = tid >> 5, l = tid & 31;
    const int wm = (w >> 1) * 16, wn = (w & 1) * 64;

    // fragment index helpers (validated in R3/R4)
    const int afr = (l & 15), afc = (l >> 4) * 8;
    const int bg = l >> 3, bRow = ((bg >> 1) << 3) + (l & 7), bc8 = (bg & 1) * 8;
    const int vkr = ((l >> 3) & 1) * 8 + (l & 7), vnc = (l >> 4) * 8;

    // ---- loaders ----
    auto issueQ = [&]() {
        const int row = tid >> 2, pl = (tid >> 1) & 1, hf = tid & 1;
        const __nv_bfloat16* s = (pl ? Ql : Qh) + zb + (size_t)(y0 + row) * DK + hf * 32;
        const uint32_t d = smaddr(Qs + row * QKST + pl * 64 + hf * 32);
        #pragma unroll
        for (int i = 0; i < 4; i++) cpa16(d + i * 16, s + i * 8);
    };
    auto issueKV = [&](const __nv_bfloat16* hi, const __nv_bfloat16* lo,
                       int kt, __nv_bfloat16* dst) {
        const int row = tid >> 1, pl = tid & 1;
        const __nv_bfloat16* s = (pl ? lo : hi) + zb + (size_t)(kt * 128 + row) * DK;
        const uint32_t d = smaddr(dst + row * QKST + pl * 64);
        #pragma unroll
        for (int i = 0; i < 8; i++) cpa16(d + i * 16, s + i * 8);
    };
    auto issueKhi = [&](int kt, __nv_bfloat16* dst) {
        const int row = tid >> 1, hf = tid & 1;
        const __nv_bfloat16* s = Kh + zb + (size_t)(kt * 128 + row) * DK + hf * 32;
        const uint32_t d = smaddr(dst + row * QKST + hf * 32);
        #pragma unroll
        for (int i = 0; i < 4; i++) cpa16(d + i * 16, s + i * 8);
    };

    if (tid < 64) rsm[tid] = 0.0f;

    float rp[2] = {0.f, 0.f};

    if (WRITE_E) {
        // ================= pass 1: bf16-only rowsums =================
        __nv_bfloat16* Kbuf[2] = { Ks, Vs };   // V buffer doubles K
        issueQ();
        issueKhi(0, Kbuf[0]);
        CP_COMMIT();
        for (int kt = 0; kt < 16; kt++) {
            if (kt < 15) { issueKhi(kt + 1, Kbuf[(kt + 1) & 1]); CP_COMMIT(); CP_WAIT(1); }
            else CP_WAIT(0);
            __syncthreads();
            const __nv_bfloat16* Kt = Kbuf[kt & 1];
            float Sacc[8][4] = {};
            #pragma unroll
            for (int kk = 0; kk < 4; kk++) {
                uint32_t Ah[4];
                ldsm4(Ah[0], Ah[1], Ah[2], Ah[3],
                      smaddr(&Qs[(wm + afr) * QKST + kk * 16 + afc]));
                #pragma unroll
                for (int g = 0; g < 4; g++) {
                    uint32_t Bh[4];
                    const int row = wn + g * 16 + bRow;
                    ldsm4(Bh[0], Bh[1], Bh[2], Bh[3],
                          smaddr(&Kt[row * QKST + kk * 16 + bc8]));
                    mma16816(Sacc[2 * g],     Ah, Bh[0], Bh[1]);
                    mma16816(Sacc[2 * g + 1], Ah, Bh[2], Bh[3]);
                }
            }
            #pragma unroll
            for (int nf = 0; nf < 8; nf++) {
                rp[0] += __expf(Sacc[nf][0] * 0.125f) + __expf(Sacc[nf][1] * 0.125f);
                rp[1] += __expf(Sacc[nf][2] * 0.125f) + __expf(Sacc[nf][3] * 0.125f);
            }
            __syncthreads();
        }
        #pragma unroll
        for (int rh = 0; rh < 2; rh++) {
            float v = rp[rh];
            v += __shfl_xor_sync(0xffffffffu, v, 1);
            v += __shfl_xor_sync(0xffffffffu, v, 2);
            if ((l & 3) == 0) atomicAdd(&rsm[wm + (l >> 2) + rh * 8], v);
        }
        __syncthreads();
        if (tid < 64) rsm[tid] = 1.0f / rsm[tid];
        __syncthreads();
    }

    float inv0 = 1.0f, inv1 = 1.0f;
    if (WRITE_E) { inv0 = rsm[wm + (l >> 2)]; inv1 = rsm[wm + (l >> 2) + 8]; }

    // ================= pass 2: full precision =================
    float acc[8][4] = {};
    if (!WRITE_E) issueQ();
    issueKV(Kh, Kl, 0, Ks);
    CP_COMMIT();
    for (int kt = 0; kt < 16; kt++) {
        issueKV(Vh, Vl, kt, Vs);
        CP_COMMIT();
        CP_WAIT(1);               // K(kt) (and Q on first iter) complete
        __syncthreads();

        // ---- S = Q K^T, full hi/lo ----
        float Sacc[8][4] = {};
        #pragma unroll
        for (int kk = 0; kk < 4; kk++) {
            uint32_t Ah[4], Al[4];
            ldsm4(Ah[0], Ah[1], Ah[2], Ah[3],
                  smaddr(&Qs[(wm + afr) * QKST + kk * 16 + afc]));
            ldsm4(Al[0], Al[1], Al[2], Al[3],
                  smaddr(&Qs[(wm + afr) * QKST + 64 + kk * 16 + afc]));
            #pragma unroll
            for (int g = 0; g < 4; g++) {
                uint32_t Bh[4], Bl[4];
                const int row = wn + g * 16 + bRow;
                ldsm4(Bh[0], Bh[1], Bh[2], Bh[3],
                      smaddr(&Ks[row * QKST + kk * 16 + bc8]));
                ldsm4(Bl[0], Bl[1], Bl[2], Bl[3],
                      smaddr(&Ks[row * QKST + 64 + kk * 16 + bc8]));
                #pragma unroll
                for (int sub = 0; sub < 2; sub++) {
                    float* c = Sacc[2 * g + sub];
                    mma16816(c, Ah, Bh[2 * sub], Bh[2 * sub + 1]);
                    mma16816(c, Ah, Bl[2 * sub], Bl[2 * sub + 1]);
                    mma16816(c, Al, Bh[2 * sub], Bh[2 * sub + 1]);
                }
            }
        }
        __syncthreads();          // K buffer free
        if (kt < 15) { issueKV(Kh, Kl, kt + 1, Ks); CP_COMMIT(); }

        // ---- exp (+normalize +write attn) + pack P ----
        uint32_t PA0[8], PA1[8], PL0[8], PL1[8];
        #pragma unroll
        for (int nf = 0; nf < 8; nf++) {
            float* c = Sacc[nf];
            float e0 = __expf(c[0] * 0.125f), e1 = __expf(c[1] * 0.125f);
            float e2 = __expf(c[2] * 0.125f), e3 = __expf(c[3] * 0.125f);
            if (WRITE_E) {
                e0 *= inv0; e1 *= inv0; e2 *= inv1; e3 *= inv1;
            } else {
                rp[0] += e0 + e1; rp[1] += e2 + e3;
            }
            __nv_bfloat16 h0 = __float2bfloat16(e0), h1 = __float2bfloat16(e1);
            __nv_bfloat16 h2 = __float2bfloat16(e2), h3 = __float2bfloat16(e3);
            PA0[nf] = packbf(__bfloat162float(h0), __bfloat162float(h1));
            PA1[nf] = packbf(__bfloat162float(h2), __bfloat162float(h3));
            PL0[nf] = packbf(e0 - __bfloat162float(h0), e1 - __bfloat162float(h1));
            PL1[nf] = packbf(e2 - __bfloat162float(h2), e3 - __bfloat162float(h3));
            if (WRITE_E) {
                const int grow = y0 + wm + (l >> 2);
                const int gcol = kt * 128 + wn + nf * 8 + 2 * (l & 3);
                *(float2*)&attn[((size_t)z * S + grow) * S + gcol] = make_float2(e0, e1);
                *(float2*)&attn[((size_t)z * S + grow + 8) * S + gcol] = make_float2(e2, e3);
            }
        }

        if (kt < 15) CP_WAIT(1); else CP_WAIT(0);   // V(kt) complete
        __syncthreads();

        // ---- ctx += P @ V over warp's k-half ----
        #pragma unroll
        for (int j = 0; j < 4; j++) {
            uint32_t Aph[4], Apl[4];
            Aph[0] = PA0[2 * j];     Aph[1] = PA1[2 * j];
            Aph[2] = PA0[2 * j + 1]; Aph[3] = PA1[2 * j + 1];
            Apl[0] = PL0[2 * j];     Apl[1] = PL1[2 * j];
            Apl[2] = PL0[2 * j + 1]; Apl[3] = PL1[2 * j + 1];
            #pragma unroll
            for (int g = 0; g < 4; g++) {
                uint32_t Vhf[4], Vlf[4];
                const int row = wn + j * 16 + vkr;
                ldsm4t(Vhf[0], Vhf[1], Vhf[2], Vhf[3],
                       smaddr(&Vs[row * QKST + g * 16 + vnc]));
                ldsm4t(Vlf[0], Vlf[1], Vlf[2], Vlf[3],
                       smaddr(&Vs[row * QKST + 64 + g * 16 + vnc]));
                #pragma unroll
                for (int sub = 0; sub < 2; sub++) {
                    float* c = acc[2 * g + sub];
                    mma16816(c, Aph, Vhf[2 * sub], Vhf[2 * sub + 1]);
                    mma16816(c, Aph, Vlf[2 * sub], Vlf[2 * sub + 1]);
                    mma16816(c, Apl, Vhf[2 * sub], Vhf[2 * sub + 1]);
                }
            }
        }
        __syncthreads();          // V buffer free
    }

    if (!WRITE_E) {
        #pragma unroll
        for (int rh = 0; rh < 2; rh++) {
            float v = rp[rh];
            v += __shfl_xor_sync(0xffffffffu, v, 1);
            v += __shfl_xor_sync(0xffffffffu, v, 2);
            if ((l & 3) == 0) atomicAdd(&rsm[wm + (l >> 2) + rh * 8], v);
        }
        __syncthreads();
        if (tid < 64) rsm[tid] = 1.0f / rsm[tid];
        __syncthreads();
    }

    // ---- pair-reduce ctx across the two k-half warps, store ----
    const int er = l >> 2;
    if (w & 1) {
        #pragma unroll
        for (int nf = 0; nf < 8; nf++) {
            const int r = wm + er, c = nf * 8 + 2 * (l & 3);
            *(float2*)&rbuf[r * 66 + c] = make_float2(acc[nf][0], acc[nf][1]);
            *(float2*)&rbuf[(r + 8) * 66 + c] = make_float2(acc[nf][2], acc[nf][3]);
        }
    }
    __syncthreads();
    if (!(w & 1)) {
        const int r = wm + er;
        const float s0 = WRITE_E ? 1.0f : rsm[r];
        const float s1 = WRITE_E ? 1.0f : rsm[r + 8];
        #pragma unroll
        for (int nf = 0; nf < 8; nf++) {
            const int c = nf * 8 + 2 * (l & 3);
            float2 p0 = *(float2*)&rbuf[r * 66 + c];
            float2 p1 = *(float2*)&rbuf[(r + 8) * 66 + c];
            *(float2*)&ctx[((size_t)bz * S + y0 + r) * D + hz * 64 + c] =
                make_float2((acc[nf][0] + p0.x) * s0, (acc[nf][1] + p0.y) * s0);
            *(float2*)&ctx[((size_t)bz * S + y0 + r + 8) * D + hz * 64 + c] =
                make_float2((acc[nf][2] + p1.x) * s1, (acc[nf][3] + p1.y) * s1);
        }
    }
}

// ---------------------------------------------------------------------------
extern "C" void kernel_launch(void* const* d_in, const int* in_sizes, int n_in,
                              void* d_out, int out_size)
{
    const float* query = (const float*)d_in[0];
    const float* key_i = (const float*)d_in[1];
    const float* value = (const float*)d_in[2];
    const float* w_q   = (const float*)d_in[3];
    const float* w_k   = (const float*)d_in[4];
    const float* w_v   = (const float*)d_in[5];
    const float* w_o   = (const float*)d_in[6];
    float* out = (float*)d_out;

    __nv_bfloat16 *qh, *ql, *kh, *kl, *vh, *vl;
    float *cp;
    cudaGetSymbolAddress((void**)&qh, g_qh);
    cudaGetSymbolAddress((void**)&ql, g_ql);
    cudaGetSymbolAddress((void**)&kh, g_kh);
    cudaGetSymbolAddress((void**)&kl, g_kl);
    cudaGetSymbolAddress((void**)&vh, g_vh);
    cudaGetSymbolAddress((void**)&vl, g_vl);
    cudaGetSymbolAddress((void**)&cp, g_ctx);

    const bool want_attn = ((long long)out_size >= OUT_ELEMS + ATT_ELEMS);
    float* attn = want_attn ? (out + OUT_ELEMS) : nullptr;

    const dim3 tb(256);
    const dim3 gproj(D / 128, (BATCH * S) / 128, 1);

    // q/k/v projections -> bf16 hi/lo planes, head-major [B,H,S,DK]
    gemm_nt_mma<1><<<gproj, tb>>>(query, w_q, nullptr, qh, ql, D, D, 1.0f);
    gemm_nt_mma<1><<<gproj, tb>>>(key_i, w_k, nullptr, kh, kl, D, D, 1.0f);
    gemm_nt_mma<1><<<gproj, tb>>>(value, w_v, nullptr, vh, vl, D, D, 1.0f);

    // fused attention: 64-row Q tiles, 2 CTAs/SM
    const int smem = (64 + 128 + 128) * QKST * 2 + 64 * 4;   // 87296 B
    const dim3 gf(S / 64, BH);
    if (want_attn) {
        cudaFuncSetAttribute(fused_attn<true>,
                             cudaFuncAttributeMaxDynamicSharedMemorySize, smem);
        fused_attn<true><<<gf, tb, smem>>>(qh, ql, kh, kl, vh, vl, cp, attn);
    } else {
        cudaFuncSetAttribute(fused_attn<false>,
                             cudaFuncAttributeMaxDynamicSharedMemorySize, smem);
        fused_attn<false><<<gf, tb, smem>>>(qh, ql, kh, kl, vh, vl, cp, nullptr);
    }

    // out = ctx @ Wo^T
    gemm_nt_mma<0><<<gproj, tb>>>(cp, w_o, out, nullptr, nullptr, D, D, 1.0f);
}

// round 7
// speedup vs baseline: 1.0981x; 1.0096x over previous
#include <cuda_runtime.h>
#include <cuda_bf16.h>
#include <stdint.h>

// ---------------------------------------------------------------------------
// MultiHeadSelfAttention: B=2, S=2048, D=1024, H=16, dk=64
// R6: two-pass fused attention. Pass1 = 2-mma rowsums (K-hi only, race-fixed,
//     double-buffered). Pass2 = full hi/lo precision, Q-lo in registers,
//     K double-buffered, 2 barriers/iter, exp interleaved into PV, exact
//     ctx normalization via in-pass accumulated sums.
// ---------------------------------------------------------------------------

namespace {
constexpr int BATCH = 2, S = 2048, D = 1024, H = 16, DK = 64, BH = 32;
constexpr long long OUT_ELEMS = (long long)BATCH * S * D;          // 4,194,304
constexpr long long ATT_ELEMS = (long long)BH * S * (long long)S;  // 134,217,728
constexpr int QST = 72;     // Q smem stride (hi plane only) in bf16
constexpr int KST = 136;    // K/V smem stride in bf16: 64 hi + 64 lo + 8 pad
}

// Scratch (allocation-free): bf16 hi/lo planes for q,k,v + fp32 ctx
__device__ __nv_bfloat16 g_qh[(size_t)BH * S * DK];
__device__ __nv_bfloat16 g_ql[(size_t)BH * S * DK];
__device__ __nv_bfloat16 g_kh[(size_t)BH * S * DK];
__device__ __nv_bfloat16 g_kl[(size_t)BH * S * DK];
__device__ __nv_bfloat16 g_vh[(size_t)BH * S * DK];
__device__ __nv_bfloat16 g_vl[(size_t)BH * S * DK];
__device__ float g_ctx[(size_t)BATCH * S * D];

// ------------------------------ PTX helpers --------------------------------
__device__ __forceinline__ uint32_t smaddr(const void* p) {
    return (uint32_t)__cvta_generic_to_shared(p);
}
__device__ __forceinline__ void ldsm4(uint32_t& r0, uint32_t& r1, uint32_t& r2,
                                      uint32_t& r3, uint32_t a) {
    asm volatile("ldmatrix.sync.aligned.m8n8.x4.shared.b16 {%0,%1,%2,%3}, [%4];"
                 : "=r"(r0), "=r"(r1), "=r"(r2), "=r"(r3) : "r"(a));
}
__device__ __forceinline__ void ldsm4t(uint32_t& r0, uint32_t& r1, uint32_t& r2,
                                       uint32_t& r3, uint32_t a) {
    asm volatile("ldmatrix.sync.aligned.m8n8.x4.trans.shared.b16 {%0,%1,%2,%3}, [%4];"
                 : "=r"(r0), "=r"(r1), "=r"(r2), "=r"(r3) : "r"(a));
}
__device__ __forceinline__ void mma16816(float* c, const uint32_t* a,
                                         uint32_t b0, uint32_t b1) {
    asm volatile("mma.sync.aligned.m16n8k16.row.col.f32.bf16.bf16.f32 "
                 "{%0,%1,%2,%3}, {%4,%5,%6,%7}, {%8,%9}, {%0,%1,%2,%3};"
                 : "+f"(c[0]), "+f"(c[1]), "+f"(c[2]), "+f"(c[3])
                 : "r"(a[0]), "r"(a[1]), "r"(a[2]), "r"(a[3]), "r"(b0), "r"(b1));
}
__device__ __forceinline__ uint32_t packbf(float a, float b) {
    __nv_bfloat162 t = __halves2bfloat162(__float2bfloat16(a), __float2bfloat16(b));
    return *reinterpret_cast<uint32_t*>(&t);
}
__device__ __forceinline__ void cpa16(uint32_t dst, const void* src) {
    asm volatile("cp.async.cg.shared.global [%0], [%1], 16;" :: "r"(dst), "l"(src));
}
#define CP_COMMIT() asm volatile("cp.async.commit_group;")
#define CP_WAIT(N)  asm volatile("cp.async.wait_group %0;" :: "n"(N))

// fp32 float4 -> (4x bf16 hi, 4x bf16 lo) packed as uint2 each
__device__ __forceinline__ void split4(const float4 f, uint2& hi, uint2& lo) {
    __nv_bfloat16 hx = __float2bfloat16(f.x), hy = __float2bfloat16(f.y);
    __nv_bfloat16 hz = __float2bfloat16(f.z), hw = __float2bfloat16(f.w);
    __nv_bfloat16 lx = __float2bfloat16(f.x - __bfloat162float(hx));
    __nv_bfloat16 ly = __float2bfloat16(f.y - __bfloat162float(hy));
    __nv_bfloat16 lz = __float2bfloat16(f.z - __bfloat162float(hz));
    __nv_bfloat16 lw = __float2bfloat16(f.w - __bfloat162float(hw));
    __nv_bfloat162 h01 = __halves2bfloat162(hx, hy), h23 = __halves2bfloat162(hz, hw);
    __nv_bfloat162 l01 = __halves2bfloat162(lx, ly), l23 = __halves2bfloat162(lz, lw);
    hi.x = *reinterpret_cast<uint32_t*>(&h01); hi.y = *reinterpret_cast<uint32_t*>(&h23);
    lo.x = *reinterpret_cast<uint32_t*>(&l01); lo.y = *reinterpret_cast<uint32_t*>(&l23);
}

// ---------------------------------------------------------------------------
// Dense SGEMM-on-mma (NT, 128x128 CTA, BK=16, hi/lo split) — unchanged.
// EPI=0: fp32 C row-major. EPI=1: bf16 hi/lo planes, head-major [B,H,S,DK].
// ---------------------------------------------------------------------------
template <int EPI>
__global__ void __launch_bounds__(256)
gemm_nt_mma(const float* __restrict__ A, const float* __restrict__ Bw,
            float* __restrict__ C, __nv_bfloat16* __restrict__ Chi,
            __nv_bfloat16* __restrict__ Clo, int K, int N, float alpha)
{
    constexpr int ST = 40;
    __shared__ __align__(16) __nv_bfloat16 Asm[2][128][ST];
    __shared__ __align__(16) __nv_bfloat16 Bsm[2][128][ST];

    const int tid = threadIdx.x, w = tid >> 5, l = tid & 31;
    const int m0 = blockIdx.y * 128, n0 = blockIdx.x * 128;
    const int wm = (w >> 2) * 64, wn = (w & 3) * 32;

    const int lr = l & 7;
    const int kc = (l >> 3) * 4;
    const int r0l = w * 16 + lr, r1l = r0l + 8;

    const int afr = wm + (l & 15);
    const int afc = (l >> 4) * 8;
    const int bg  = l >> 3;
    const int bfr = wn + ((bg >> 1) << 3) + (l & 7);
    const int bfc = (bg & 1) * 8;

    float4 aR0, aR1, bR0, bR1;
    float acc[4][4][4] = {};

    auto loadG = [&](int kt) {
        const size_t ko = (size_t)kt * 16 + kc;
        aR0 = *(const float4*)(A + (size_t)(m0 + r0l) * K + ko);
        aR1 = *(const float4*)(A + (size_t)(m0 + r1l) * K + ko);
        bR0 = *(const float4*)(Bw + (size_t)(n0 + r0l) * K + ko);
        bR1 = *(const float4*)(Bw + (size_t)(n0 + r1l) * K + ko);
    };
    auto storeS = [&](int buf) {
        uint2 hi, lo;
        split4(aR0, hi, lo);
        *(uint2*)&Asm[buf][r0l][kc] = hi; *(uint2*)&Asm[buf][r0l][16 + kc] = lo;
        split4(aR1, hi, lo);
        *(uint2*)&Asm[buf][r1l][kc] = hi; *(uint2*)&Asm[buf][r1l][16 + kc] = lo;
        split4(bR0, hi, lo);
        *(uint2*)&Bsm[buf][r0l][kc] = hi; *(uint2*)&Bsm[buf][r0l][16 + kc] = lo;
        split4(bR1, hi, lo);
        *(uint2*)&Bsm[buf][r1l][kc] = hi; *(uint2*)&Bsm[buf][r1l][16 + kc] = lo;
    };

    loadG(0); storeS(0); __syncthreads();
    const int KT = K / 16;
    int buf = 0;
    for (int kt = 0; kt < KT; kt++) {
        const bool more = (kt + 1 < KT);
        if (more) loadG(kt + 1);

        uint32_t Bh[8], Bl[8];
        ldsm4(Bh[0], Bh[1], Bh[2], Bh[3], smaddr(&Bsm[buf][bfr][bfc]));
        ldsm4(Bh[4], Bh[5], Bh[6], Bh[7], smaddr(&Bsm[buf][bfr + 16][bfc]));
        ldsm4(Bl[0], Bl[1], Bl[2], Bl[3], smaddr(&Bsm[buf][bfr][bfc + 16]));
        ldsm4(Bl[4], Bl[5], Bl[6], Bl[7], smaddr(&Bsm[buf][bfr + 16][bfc + 16]));

        #pragma unroll
        for (int mf = 0; mf < 4; mf++) {
            uint32_t Ah[4], Al[4];
            ldsm4(Ah[0], Ah[1], Ah[2], Ah[3], smaddr(&Asm[buf][afr + mf * 16][afc]));
            ldsm4(Al[0], Al[1], Al[2], Al[3], smaddr(&Asm[buf][afr + mf * 16][afc + 16]));
            #pragma unroll
            for (int nf = 0; nf < 4; nf++) {
                float* c = acc[mf][nf];
                mma16816(c, Ah, Bh[nf * 2], Bh[nf * 2 + 1]);
                mma16816(c, Ah, Bl[nf * 2], Bl[nf * 2 + 1]);
                mma16816(c, Al, Bh[nf * 2], Bh[nf * 2 + 1]);
            }
        }
        if (more) { buf ^= 1; storeS(buf); __syncthreads(); }
    }

    const int er = l >> 2, ec = (l & 3) * 2;
    #pragma unroll
    for (int mf = 0; mf < 4; mf++) {
        #pragma unroll
        for (int nf = 0; nf < 4; nf++) {
            const float* c = acc[mf][nf];
            const int rr = m0 + wm + mf * 16 + er;
            const int cc = n0 + wn + nf * 8 + ec;
            if (EPI == 1) {
                const int hh = cc >> 6, dd = cc & 63;
                const int bb = rr >> 11, ss = rr & (S - 1);
                const int rr2 = rr + 8, bb2 = rr2 >> 11, ss2 = rr2 & (S - 1);
                const size_t i0 = (((size_t)bb  * H + hh) * S + ss)  * DK + dd;
                const size_t i1 = (((size_t)bb2 * H + hh) * S + ss2) * DK + dd;
                __nv_bfloat16 h0 = __float2bfloat16(c[0]), h1 = __float2bfloat16(c[1]);
                __nv_bfloat16 h2 = __float2bfloat16(c[2]), h3 = __float2bfloat16(c[3]);
                *(uint32_t*)&Chi[i0] = packbf(__bfloat162float(h0), __bfloat162float(h1));
                *(uint32_t*)&Clo[i0] = packbf(c[0] - __bfloat162float(h0),
                                              c[1] - __bfloat162float(h1));
                *(uint32_t*)&Chi[i1] = packbf(__bfloat162float(h2), __bfloat162float(h3));
                *(uint32_t*)&Clo[i1] = packbf(c[2] - __bfloat162float(h2),
                                              c[3] - __bfloat162float(h3));
            } else {
                *(float2*)&C[(size_t)rr * N + cc] =
                    make_float2(c[0] * alpha, c[1] * alpha);
                *(float2*)&C[(size_t)(rr + 8) * N + cc] =
                    make_float2(c[2] * alpha, c[3] * alpha);
            }
        }
    }
}

// ---------------------------------------------------------------------------
// Fused attention. Grid (S/64, BH); 256 thr / 8 warps; 2 CTAs/SM.
// Warp tile: 16(m) x 64(n k-half). Q-hi in smem, Q-lo fragments in registers.
// ---------------------------------------------------------------------------
template <bool WRITE_E>
__global__ void __launch_bounds__(256, 2)
fused_attn(const __nv_bfloat16* __restrict__ Qh, const __nv_bfloat16* __restrict__ Ql,
           const __nv_bfloat16* __restrict__ Kh, const __nv_bfloat16* __restrict__ Kl,
           const __nv_bfloat16* __restrict__ Vh, const __nv_bfloat16* __restrict__ Vl,
           float* __restrict__ ctx, float* __restrict__ attn)
{
    extern __shared__ __align__(16) char sm[];
    __nv_bfloat16* Qs  = (__nv_bfloat16*)sm;         // [64][72] hi only
    __nv_bfloat16* KB0 = Qs + 64 * QST;              // [128][136]
    __nv_bfloat16* KB1 = KB0 + 128 * KST;            // [128][136]
    __nv_bfloat16* Vs  = KB1 + 128 * KST;            // [128][136]
    float* rsm  = (float*)(Vs + 128 * KST);          // [64] pass1 inv
    float* rsm2 = rsm + 64;                          // [64] exact sums
    float* rbuf = (float*)KB0;                       // epilogue reuse

    const int z = blockIdx.y, y0 = blockIdx.x * 64;
    const int bz = z >> 4, hz = z & 15;
    const size_t zb = (size_t)z * S * DK;

    const int tid = threadIdx.x, w = tid >> 5, l = tid & 31;
    const int wm = (w >> 1) * 16, wn = (w & 1) * 64;

    const int afr = (l & 15), afc = (l >> 4) * 8;
    const int bg = l >> 3, bRow = ((bg >> 1) << 3) + (l & 7), bc8 = (bg & 1) * 8;
    const int vkr = ((l >> 3) & 1) * 8 + (l & 7), vnc = (l >> 4) * 8;

    // ---- loaders ----
    const int qrow = tid >> 2, qc = (tid & 3) * 16;     // Q: 64 rows x 64 cols
    auto issueQhi = [&]() {
        const __nv_bfloat16* s = Qh + zb + (size_t)(y0 + qrow) * DK + qc;
        const uint32_t d = smaddr(Qs + qrow * QST + qc);
        cpa16(d, s); cpa16(d + 16, s + 8);
    };
    auto stageQlo = [&]() {                             // into Vs temporarily
        const __nv_bfloat16* s = Ql + zb + (size_t)(y0 + qrow) * DK + qc;
        const uint32_t d = smaddr(Vs + qrow * KST + qc);
        cpa16(d, s); cpa16(d + 16, s + 8);
    };
    const int krow = tid >> 1;
    auto issueK = [&](int kt, __nv_bfloat16* dst) {     // hi+lo planes
        const int pl = tid & 1;
        const __nv_bfloat16* s = (pl ? Kl : Kh) + zb + (size_t)(kt * 128 + krow) * DK;
        const uint32_t d = smaddr(dst + krow * KST + pl * 64);
        #pragma unroll
        for (int i = 0; i < 8; i++) cpa16(d + i * 16, s + i * 8);
    };
    auto issueKhi = [&](int kt, __nv_bfloat16* dst) {   // hi plane only
        const int hf = tid & 1;
        const __nv_bfloat16* s = Kh + zb + (size_t)(kt * 128 + krow) * DK + hf * 32;
        const uint32_t d = smaddr(dst + krow * KST + hf * 32);
        #pragma unroll
        for (int i = 0; i < 4; i++) cpa16(d + i * 16, s + i * 8);
    };
    auto issueV = [&](int kt) {
        const int pl = tid & 1;
        const __nv_bfloat16* s = (pl ? Vl : Vh) + zb + (size_t)(kt * 128 + krow) * DK;
        const uint32_t d = smaddr(Vs + krow * KST + pl * 64);
        #pragma unroll
        for (int i = 0; i < 8; i++) cpa16(d + i * 16, s + i * 8);
    };

    if (tid < 64) { rsm[tid] = 0.0f; rsm2[tid] = 0.0f; }

    // ---- Q: hi to smem, lo staged then kept in registers ----
    issueQhi(); stageQlo(); CP_COMMIT();
    CP_WAIT(0); __syncthreads();
    uint32_t Alr[4][4];
    #pragma unroll
    for (int kk = 0; kk < 4; kk++)
        ldsm4(Alr[kk][0], Alr[kk][1], Alr[kk][2], Alr[kk][3],
              smaddr(&Vs[(wm + afr) * KST + kk * 16 + afc]));
    __syncthreads();   // Vs free

    float rp0 = 0.f, rp1 = 0.f;

    if (WRITE_E) {
        // ============ pass 1: 2-mma rowsums (K-hi only) ============
        issueKhi(0, KB0); CP_COMMIT();
        for (int kt = 0; kt < 16; kt++) {
            CP_WAIT(0); __syncthreads();
            if (kt < 15) { issueKhi(kt + 1, (kt & 1) ? KB0 : KB1); CP_COMMIT(); }
            const __nv_bfloat16* Kt = (kt & 1) ? KB1 : KB0;
            float Sacc[8][4] = {};
            #pragma unroll
            for (int kk = 0; kk < 4; kk++) {
                uint32_t Ah[4];
                ldsm4(Ah[0], Ah[1], Ah[2], Ah[3],
                      smaddr(&Qs[(wm + afr) * QST + kk * 16 + afc]));
                #pragma unroll
                for (int g = 0; g < 4; g++) {
                    uint32_t Bh[4];
                    ldsm4(Bh[0], Bh[1], Bh[2], Bh[3],
                          smaddr(&Kt[(wn + g * 16 + bRow) * KST + kk * 16 + bc8]));
                    mma16816(Sacc[2 * g],     Ah,      Bh[0], Bh[1]);
                    mma16816(Sacc[2 * g],     Alr[kk], Bh[0], Bh[1]);
                    mma16816(Sacc[2 * g + 1], Ah,      Bh[2], Bh[3]);
                    mma16816(Sacc[2 * g + 1], Alr[kk], Bh[2], Bh[3]);
                }
            }
            #pragma unroll
            for (int nf = 0; nf < 8; nf++) {
                rp0 += __expf(Sacc[nf][0] * 0.125f) + __expf(Sacc[nf][1] * 0.125f);
                rp1 += __expf(Sacc[nf][2] * 0.125f) + __expf(Sacc[nf][3] * 0.125f);
            }
        }
        {
            float v0 = rp0, v1 = rp1;
            v0 += __shfl_xor_sync(0xffffffffu, v0, 1);
            v0 += __shfl_xor_sync(0xffffffffu, v0, 2);
            v1 += __shfl_xor_sync(0xffffffffu, v1, 1);
            v1 += __shfl_xor_sync(0xffffffffu, v1, 2);
            if ((l & 3) == 0) {
                atomicAdd(&rsm[wm + (l >> 2)], v0);
                atomicAdd(&rsm[wm + (l >> 2) + 8], v1);
            }
        }
        __syncthreads();
        if (tid < 64) rsm[tid] = 1.0f / rsm[tid];
        __syncthreads();
    }

    float inv0 = 1.0f, inv1 = 1.0f;
    if (WRITE_E) { inv0 = rsm[wm + (l >> 2)]; inv1 = rsm[wm + (l >> 2) + 8]; }
    rp0 = rp1 = 0.f;

    // ============ pass 2: full precision + PV ============
    float acc[8][4] = {};
    issueK(0, KB0); CP_COMMIT();
    for (int kt = 0; kt < 16; kt++) {
        CP_WAIT(0); __syncthreads();          // b1: K(kt) ready, PV(kt-1) done
        issueV(kt); CP_COMMIT();
        const __nv_bfloat16* Kt = (kt & 1) ? KB1 : KB0;

        float Sacc[8][4] = {};
        #pragma unroll
        for (int kk = 0; kk < 4; kk++) {
            uint32_t Ah[4];
            ldsm4(Ah[0], Ah[1], Ah[2], Ah[3],
                  smaddr(&Qs[(wm + afr) * QST + kk * 16 + afc]));
            #pragma unroll
            for (int g = 0; g < 4; g++) {
                uint32_t Bh[4], Bl[4];
                const int row = wn + g * 16 + bRow;
                ldsm4(Bh[0], Bh[1], Bh[2], Bh[3],
                      smaddr(&Kt[row * KST + kk * 16 + bc8]));
                ldsm4(Bl[0], Bl[1], Bl[2], Bl[3],
                      smaddr(&Kt[row * KST + 64 + kk * 16 + bc8]));
                #pragma unroll
                for (int sub = 0; sub < 2; sub++) {
                    float* c = Sacc[2 * g + sub];
                    mma16816(c, Ah,      Bh[2 * sub], Bh[2 * sub + 1]);
                    mma16816(c, Ah,      Bl[2 * sub], Bl[2 * sub + 1]);
                    mma16816(c, Alr[kk], Bh[2 * sub], Bh[2 * sub + 1]);
                }
            }
        }
        if (kt < 15) { issueK(kt + 1, (kt & 1) ? KB0 : KB1); CP_COMMIT(); }
        CP_WAIT(1); __syncthreads();          // b2: V(kt) ready

        // ---- exp interleaved with PV, j = k16 chunk of this 128-col tile ----
        #pragma unroll
        for (int j = 0; j < 4; j++) {
            uint32_t Aph[4], Apl[4];
            #pragma unroll
            for (int t = 0; t < 2; t++) {
                float* c = Sacc[2 * j + t];
                float e0 = __expf(c[0] * 0.125f), e1 = __expf(c[1] * 0.125f);
                float e2 = __expf(c[2] * 0.125f), e3 = __expf(c[3] * 0.125f);
                if (WRITE_E) { e0 *= inv0; e1 *= inv0; e2 *= inv1; e3 *= inv1; }
                rp0 += e0 + e1; rp1 += e2 + e3;
                __nv_bfloat16 h0 = __float2bfloat16(e0), h1 = __float2bfloat16(e1);
                __nv_bfloat16 h2 = __float2bfloat16(e2), h3 = __float2bfloat16(e3);
                Aph[2 * t]     = packbf(__bfloat162float(h0), __bfloat162float(h1));
                Aph[2 * t + 1] = packbf(__bfloat162float(h2), __bfloat162float(h3));
                Apl[2 * t]     = packbf(e0 - __bfloat162float(h0), e1 - __bfloat162float(h1));
                Apl[2 * t + 1] = packbf(e2 - __bfloat162float(h2), e3 - __bfloat162float(h3));
                if (WRITE_E) {
                    const int grow = y0 + wm + (l >> 2);
                    const int gcol = kt * 128 + wn + (2 * j + t) * 8 + 2 * (l & 3);
                    *(float2*)&attn[((size_t)z * S + grow) * S + gcol] = make_float2(e0, e1);
                    *(float2*)&attn[((size_t)z * S + grow + 8) * S + gcol] = make_float2(e2, e3);
                }
            }
            #pragma unroll
            for (int g = 0; g < 4; g++) {
                uint32_t Vhf[4], Vlf[4];
                const int row = wn + j * 16 + vkr;
                ldsm4t(Vhf[0], Vhf[1], Vhf[2], Vhf[3],
                       smaddr(&Vs[row * KST + g * 16 + vnc]));
                ldsm4t(Vlf[0], Vlf[1], Vlf[2], Vlf[3],
                       smaddr(&Vs[row * KST + 64 + g * 16 + vnc]));
                #pragma unroll
                for (int sub = 0; sub < 2; sub++) {
                    float* c = acc[2 * g + sub];
                    mma16816(c, Aph, Vhf[2 * sub], Vhf[2 * sub + 1]);
                    mma16816(c, Aph, Vlf[2 * sub], Vlf[2 * sub + 1]);
                    mma16816(c, Apl, Vhf[2 * sub], Vhf[2 * sub + 1]);
                }
            }
        }
    }

    // ---- exact row sums of (possibly pre-normalized) P -> rsm2 ----
    {
        float v0 = rp0, v1 = rp1;
        v0 += __shfl_xor_sync(0xffffffffu, v0, 1);
        v0 += __shfl_xor_sync(0xffffffffu, v0, 2);
        v1 += __shfl_xor_sync(0xffffffffu, v1, 1);
        v1 += __shfl_xor_sync(0xffffffffu, v1, 2);
        if ((l & 3) == 0) {
            atomicAdd(&rsm2[wm + (l >> 2)], v0);
            atomicAdd(&rsm2[wm + (l >> 2) + 8], v1);
        }
    }
    __syncthreads();
    if (tid < 64) rsm2[tid] = 1.0f / rsm2[tid];
    __syncthreads();

    // ---- pair-reduce ctx across the two k-half warps, exact scale, store ----
    const int er = l >> 2;
    if (w & 1) {
        #pragma unroll
        for (int nf = 0; nf < 8; nf++) {
            const int r = wm + er, c = nf * 8 + 2 * (l & 3);
            *(float2*)&rbuf[r * 66 + c] = make_float2(acc[nf][0], acc[nf][1]);
            *(float2*)&rbuf[(r + 8) * 66 + c] = make_float2(acc[nf][2], acc[nf][3]);
        }
    }
    __syncthreads();
    if (!(w & 1)) {
        const int r = wm + er;
        const float s0 = rsm2[r], s1 = rsm2[r + 8];
        #pragma unroll
        for (int nf = 0; nf < 8; nf++) {
            const int c = nf * 8 + 2 * (l & 3);
            float2 p0 = *(float2*)&rbuf[r * 66 + c];
            float2 p1 = *(float2*)&rbuf[(r + 8) * 66 + c];
            *(float2*)&ctx[((size_t)bz * S + y0 + r) * D + hz * 64 + c] =
                make_float2((acc[nf][0] + p0.x) * s0, (acc[nf][1] + p0.y) * s0);
            *(float2*)&ctx[((size_t)bz * S + y0 + r + 8) * D + hz * 64 + c] =
                make_float2((acc[nf][2] + p1.x) * s1, (acc[nf][3] + p1.y) * s1);
        }
    }
}

// ---------------------------------------------------------------------------
extern "C" void kernel_launch(void* const* d_in, const int* in_sizes, int n_in,
                              void* d_out, int out_size)
{
    const float* query = (const float*)d_in[0];
    const float* key_i = (const float*)d_in[1];
    const float* value = (const float*)d_in[2];
    const float* w_q   = (const float*)d_in[3];
    const float* w_k   = (const float*)d_in[4];
    const float* w_v   = (const float*)d_in[5];
    const float* w_o   = (const float*)d_in[6];
    float* out = (float*)d_out;

    __nv_bfloat16 *qh, *ql, *kh, *kl, *vh, *vl;
    float *cp;
    cudaGetSymbolAddress((void**)&qh, g_qh);
    cudaGetSymbolAddress((void**)&ql, g_ql);
    cudaGetSymbolAddress((void**)&kh, g_kh);
    cudaGetSymbolAddress((void**)&kl, g_kl);
    cudaGetSymbolAddress((void**)&vh, g_vh);
    cudaGetSymbolAddress((void**)&vl, g_vl);
    cudaGetSymbolAddress((void**)&cp, g_ctx);

    const bool want_attn = ((long long)out_size >= OUT_ELEMS + ATT_ELEMS);
    float* attn = want_attn ? (out + OUT_ELEMS) : nullptr;

    const dim3 tb(256);
    const dim3 gproj(D / 128, (BATCH * S) / 128, 1);

    gemm_nt_mma<1><<<gproj, tb>>>(query, w_q, nullptr, qh, ql, D, D, 1.0f);
    gemm_nt_mma<1><<<gproj, tb>>>(key_i, w_k, nullptr, kh, kl, D, D, 1.0f);
    gemm_nt_mma<1><<<gproj, tb>>>(value, w_v, nullptr, vh, vl, D, D, 1.0f);

    // fused attention: Q 64-row tiles, 2 CTAs/SM, 111.5 KB smem
    const int smem = (64 * QST + 3 * 128 * KST) * 2 + 128 * 4;   // 114176 B
    const dim3 gf(S / 64, BH);
    if (want_attn) {
        cudaFuncSetAttribute(fused_attn<true>,
                             cudaFuncAttributeMaxDynamicSharedMemorySize, smem);
        fused_attn<true><<<gf, tb, smem>>>(qh, ql, kh, kl, vh, vl, cp, attn);
    } else {
        cudaFuncSetAttribute(fused_attn<false>,
                             cudaFuncAttributeMaxDynamicSharedMemorySize, smem);
        fused_attn<false><<<gf, tb, smem>>>(qh, ql, kh, kl, vh, vl, cp, nullptr);
    }

    gemm_nt_mma<0><<<gproj, tb>>>(cp, w_o, out, nullptr, nullptr, D, D, 1.0f);
}

// round 8
// speedup vs baseline: 1.1129x; 1.0135x over previous
#include <cuda_runtime.h>
#include <cuda_bf16.h>
#include <stdint.h>

// ---------------------------------------------------------------------------
// MultiHeadSelfAttention: B=2, S=2048, D=1024, H=16, dk=64
// R7: R6 structure with (a) fixed kt==15 V-tile cp.async race (out error),
//     (b) pass1 distance-2 prefetch through 3 rotating K buffers,
//     (c) exact ctx normalization via in-pass sums (kept from R6).
// ---------------------------------------------------------------------------

namespace {
constexpr int BATCH = 2, S = 2048, D = 1024, H = 16, DK = 64, BH = 32;
constexpr long long OUT_ELEMS = (long long)BATCH * S * D;          // 4,194,304
constexpr long long ATT_ELEMS = (long long)BH * S * (long long)S;  // 134,217,728
constexpr int QST = 72;     // Q smem stride (hi plane only) in bf16
constexpr int KST = 136;    // K/V smem stride in bf16: 64 hi + 64 lo + 8 pad
}

// Scratch (allocation-free): bf16 hi/lo planes for q,k,v + fp32 ctx
__device__ __nv_bfloat16 g_qh[(size_t)BH * S * DK];
__device__ __nv_bfloat16 g_ql[(size_t)BH * S * DK];
__device__ __nv_bfloat16 g_kh[(size_t)BH * S * DK];
__device__ __nv_bfloat16 g_kl[(size_t)BH * S * DK];
__device__ __nv_bfloat16 g_vh[(size_t)BH * S * DK];
__device__ __nv_bfloat16 g_vl[(size_t)BH * S * DK];
__device__ float g_ctx[(size_t)BATCH * S * D];

// ------------------------------ PTX helpers --------------------------------
__device__ __forceinline__ uint32_t smaddr(const void* p) {
    return (uint32_t)__cvta_generic_to_shared(p);
}
__device__ __forceinline__ void ldsm4(uint32_t& r0, uint32_t& r1, uint32_t& r2,
                                      uint32_t& r3, uint32_t a) {
    asm volatile("ldmatrix.sync.aligned.m8n8.x4.shared.b16 {%0,%1,%2,%3}, [%4];"
                 : "=r"(r0), "=r"(r1), "=r"(r2), "=r"(r3) : "r"(a));
}
__device__ __forceinline__ void ldsm4t(uint32_t& r0, uint32_t& r1, uint32_t& r2,
                                       uint32_t& r3, uint32_t a) {
    asm volatile("ldmatrix.sync.aligned.m8n8.x4.trans.shared.b16 {%0,%1,%2,%3}, [%4];"
                 : "=r"(r0), "=r"(r1), "=r"(r2), "=r"(r3) : "r"(a));
}
__device__ __forceinline__ void mma16816(float* c, const uint32_t* a,
                                         uint32_t b0, uint32_t b1) {
    asm volatile("mma.sync.aligned.m16n8k16.row.col.f32.bf16.bf16.f32 "
                 "{%0,%1,%2,%3}, {%4,%5,%6,%7}, {%8,%9}, {%0,%1,%2,%3};"
                 : "+f"(c[0]), "+f"(c[1]), "+f"(c[2]), "+f"(c[3])
                 : "r"(a[0]), "r"(a[1]), "r"(a[2]), "r"(a[3]), "r"(b0), "r"(b1));
}
__device__ __forceinline__ uint32_t packbf(float a, float b) {
    __nv_bfloat162 t = __halves2bfloat162(__float2bfloat16(a), __float2bfloat16(b));
    return *reinterpret_cast<uint32_t*>(&t);
}
__device__ __forceinline__ void cpa16(uint32_t dst, const void* src) {
    asm volatile("cp.async.cg.shared.global [%0], [%1], 16;" :: "r"(dst), "l"(src));
}
#define CP_COMMIT() asm volatile("cp.async.commit_group;")
#define CP_WAIT(N)  asm volatile("cp.async.wait_group %0;" :: "n"(N))

// fp32 float4 -> (4x bf16 hi, 4x bf16 lo) packed as uint2 each
__device__ __forceinline__ void split4(const float4 f, uint2& hi, uint2& lo) {
    __nv_bfloat16 hx = __float2bfloat16(f.x), hy = __float2bfloat16(f.y);
    __nv_bfloat16 hz = __float2bfloat16(f.z), hw = __float2bfloat16(f.w);
    __nv_bfloat16 lx = __float2bfloat16(f.x - __bfloat162float(hx));
    __nv_bfloat16 ly = __float2bfloat16(f.y - __bfloat162float(hy));
    __nv_bfloat16 lz = __float2bfloat16(f.z - __bfloat162float(hz));
    __nv_bfloat16 lw = __float2bfloat16(f.w - __bfloat162float(hw));
    __nv_bfloat162 h01 = __halves2bfloat162(hx, hy), h23 = __halves2bfloat162(hz, hw);
    __nv_bfloat162 l01 = __halves2bfloat162(lx, ly), l23 = __halves2bfloat162(lz, lw);
    hi.x = *reinterpret_cast<uint32_t*>(&h01); hi.y = *reinterpret_cast<uint32_t*>(&h23);
    lo.x = *reinterpret_cast<uint32_t*>(&l01); lo.y = *reinterpret_cast<uint32_t*>(&l23);
}

// ---------------------------------------------------------------------------
// Dense SGEMM-on-mma (NT, 128x128 CTA, BK=16, hi/lo split) — unchanged.
// EPI=0: fp32 C row-major. EPI=1: bf16 hi/lo planes, head-major [B,H,S,DK].
// ---------------------------------------------------------------------------
template <int EPI>
__global__ void __launch_bounds__(256)
gemm_nt_mma(const float* __restrict__ A, const float* __restrict__ Bw,
            float* __restrict__ C, __nv_bfloat16* __restrict__ Chi,
            __nv_bfloat16* __restrict__ Clo, int K, int N, float alpha)
{
    constexpr int ST = 40;
    __shared__ __align__(16) __nv_bfloat16 Asm[2][128][ST];
    __shared__ __align__(16) __nv_bfloat16 Bsm[2][128][ST];

    const int tid = threadIdx.x, w = tid >> 5, l = tid & 31;
    const int m0 = blockIdx.y * 128, n0 = blockIdx.x * 128;
    const int wm = (w >> 2) * 64, wn = (w & 3) * 32;

    const int lr = l & 7;
    const int kc = (l >> 3) * 4;
    const int r0l = w * 16 + lr, r1l = r0l + 8;

    const int afr = wm + (l & 15);
    const int afc = (l >> 4) * 8;
    const int bg  = l >> 3;
    const int bfr = wn + ((bg >> 1) << 3) + (l & 7);
    const int bfc = (bg & 1) * 8;

    float4 aR0, aR1, bR0, bR1;
    float acc[4][4][4] = {};

    auto loadG = [&](int kt) {
        const size_t ko = (size_t)kt * 16 + kc;
        aR0 = *(const float4*)(A + (size_t)(m0 + r0l) * K + ko);
        aR1 = *(const float4*)(A + (size_t)(m0 + r1l) * K + ko);
        bR0 = *(const float4*)(Bw + (size_t)(n0 + r0l) * K + ko);
        bR1 = *(const float4*)(Bw + (size_t)(n0 + r1l) * K + ko);
    };
    auto storeS = [&](int buf) {
        uint2 hi, lo;
        split4(aR0, hi, lo);
        *(uint2*)&Asm[buf][r0l][kc] = hi; *(uint2*)&Asm[buf][r0l][16 + kc] = lo;
        split4(aR1, hi, lo);
        *(uint2*)&Asm[buf][r1l][kc] = hi; *(uint2*)&Asm[buf][r1l][16 + kc] = lo;
        split4(bR0, hi, lo);
        *(uint2*)&Bsm[buf][r0l][kc] = hi; *(uint2*)&Bsm[buf][r0l][16 + kc] = lo;
        split4(bR1, hi, lo);
        *(uint2*)&Bsm[buf][r1l][kc] = hi; *(uint2*)&Bsm[buf][r1l][16 + kc] = lo;
    };

    loadG(0); storeS(0); __syncthreads();
    const int KT = K / 16;
    int buf = 0;
    for (int kt = 0; kt < KT; kt++) {
        const bool more = (kt + 1 < KT);
        if (more) loadG(kt + 1);

        uint32_t Bh[8], Bl[8];
        ldsm4(Bh[0], Bh[1], Bh[2], Bh[3], smaddr(&Bsm[buf][bfr][bfc]));
        ldsm4(Bh[4], Bh[5], Bh[6], Bh[7], smaddr(&Bsm[buf][bfr + 16][bfc]));
        ldsm4(Bl[0], Bl[1], Bl[2], Bl[3], smaddr(&Bsm[buf][bfr][bfc + 16]));
        ldsm4(Bl[4], Bl[5], Bl[6], Bl[7], smaddr(&Bsm[buf][bfr + 16][bfc + 16]));

        #pragma unroll
        for (int mf = 0; mf < 4; mf++) {
            uint32_t Ah[4], Al[4];
            ldsm4(Ah[0], Ah[1], Ah[2], Ah[3], smaddr(&Asm[buf][afr + mf * 16][afc]));
            ldsm4(Al[0], Al[1], Al[2], Al[3], smaddr(&Asm[buf][afr + mf * 16][afc + 16]));
            #pragma unroll
            for (int nf = 0; nf < 4; nf++) {
                float* c = acc[mf][nf];
                mma16816(c, Ah, Bh[nf * 2], Bh[nf * 2 + 1]);
                mma16816(c, Ah, Bl[nf * 2], Bl[nf * 2 + 1]);
                mma16816(c, Al, Bh[nf * 2], Bh[nf * 2 + 1]);
            }
        }
        if (more) { buf ^= 1; storeS(buf); __syncthreads(); }
    }

    const int er = l >> 2, ec = (l & 3) * 2;
    #pragma unroll
    for (int mf = 0; mf < 4; mf++) {
        #pragma unroll
        for (int nf = 0; nf < 4; nf++) {
            const float* c = acc[mf][nf];
            const int rr = m0 + wm + mf * 16 + er;
            const int cc = n0 + wn + nf * 8 + ec;
            if (EPI == 1) {
                const int hh = cc >> 6, dd = cc & 63;
                const int bb = rr >> 11, ss = rr & (S - 1);
                const int rr2 = rr + 8, bb2 = rr2 >> 11, ss2 = rr2 & (S - 1);
                const size_t i0 = (((size_t)bb  * H + hh) * S + ss)  * DK + dd;
                const size_t i1 = (((size_t)bb2 * H + hh) * S + ss2) * DK + dd;
                __nv_bfloat16 h0 = __float2bfloat16(c[0]), h1 = __float2bfloat16(c[1]);
                __nv_bfloat16 h2 = __float2bfloat16(c[2]), h3 = __float2bfloat16(c[3]);
                *(uint32_t*)&Chi[i0] = packbf(__bfloat162float(h0), __bfloat162float(h1));
                *(uint32_t*)&Clo[i0] = packbf(c[0] - __bfloat162float(h0),
                                              c[1] - __bfloat162float(h1));
                *(uint32_t*)&Chi[i1] = packbf(__bfloat162float(h2), __bfloat162float(h3));
                *(uint32_t*)&Clo[i1] = packbf(c[2] - __bfloat162float(h2),
                                              c[3] - __bfloat162float(h3));
            } else {
                *(float2*)&C[(size_t)rr * N + cc] =
                    make_float2(c[0] * alpha, c[1] * alpha);
                *(float2*)&C[(size_t)(rr + 8) * N + cc] =
                    make_float2(c[2] * alpha, c[3] * alpha);
            }
        }
    }
}

// ---------------------------------------------------------------------------
// Fused attention. Grid (S/64, BH); 256 thr / 8 warps; 2 CTAs/SM.
// Warp tile: 16(m) x 64(n k-half). Q-hi in smem, Q-lo fragments in registers.
// ---------------------------------------------------------------------------
template <bool WRITE_E>
__global__ void __launch_bounds__(256, 2)
fused_attn(const __nv_bfloat16* __restrict__ Qh, const __nv_bfloat16* __restrict__ Ql,
           const __nv_bfloat16* __restrict__ Kh, const __nv_bfloat16* __restrict__ Kl,
           const __nv_bfloat16* __restrict__ Vh, const __nv_bfloat16* __restrict__ Vl,
           float* __restrict__ ctx, float* __restrict__ attn)
{
    extern __shared__ __align__(16) char sm[];
    __nv_bfloat16* Qs  = (__nv_bfloat16*)sm;         // [64][72] hi only
    __nv_bfloat16* KB0 = Qs + 64 * QST;              // [128][136]
    __nv_bfloat16* KB1 = KB0 + 128 * KST;            // [128][136]
    __nv_bfloat16* Vs  = KB1 + 128 * KST;            // [128][136]
    float* rsm  = (float*)(Vs + 128 * KST);          // [64] pass1 inv
    float* rsm2 = rsm + 64;                          // [64] exact sums
    float* rbuf = (float*)KB0;                       // epilogue reuse

    const int z = blockIdx.y, y0 = blockIdx.x * 64;
    const int bz = z >> 4, hz = z & 15;
    const size_t zb = (size_t)z * S * DK;

    const int tid = threadIdx.x, w = tid >> 5, l = tid & 31;
    const int wm = (w >> 1) * 16, wn = (w & 1) * 64;

    const int afr = (l & 15), afc = (l >> 4) * 8;
    const int bg = l >> 3, bRow = ((bg >> 1) << 3) + (l & 7), bc8 = (bg & 1) * 8;
    const int vkr = ((l >> 3) & 1) * 8 + (l & 7), vnc = (l >> 4) * 8;

    // ---- loaders ----
    const int qrow = tid >> 2, qc = (tid & 3) * 16;     // Q: 64 rows x 64 cols
    auto issueQhi = [&]() {
        const __nv_bfloat16* s = Qh + zb + (size_t)(y0 + qrow) * DK + qc;
        const uint32_t d = smaddr(Qs + qrow * QST + qc);
        cpa16(d, s); cpa16(d + 16, s + 8);
    };
    auto stageQlo = [&]() {                             // into Vs temporarily
        const __nv_bfloat16* s = Ql + zb + (size_t)(y0 + qrow) * DK + qc;
        const uint32_t d = smaddr(Vs + qrow * KST + qc);
        cpa16(d, s); cpa16(d + 16, s + 8);
    };
    const int krow = tid >> 1;
    auto issueK = [&](int kt, __nv_bfloat16* dst) {     // hi+lo planes
        const int pl = tid & 1;
        const __nv_bfloat16* s = (pl ? Kl : Kh) + zb + (size_t)(kt * 128 + krow) * DK;
        const uint32_t d = smaddr(dst + krow * KST + pl * 64);
        #pragma unroll
        for (int i = 0; i < 8; i++) cpa16(d + i * 16, s + i * 8);
    };
    auto issueKhi = [&](int kt, __nv_bfloat16* dst) {   // hi plane only
        const int hf = tid & 1;
        const __nv_bfloat16* s = Kh + zb + (size_t)(kt * 128 + krow) * DK + hf * 32;
        const uint32_t d = smaddr(dst + krow * KST + hf * 32);
        #pragma unroll
        for (int i = 0; i < 4; i++) cpa16(d + i * 16, s + i * 8);
    };
    auto issueV = [&](int kt) {
        const int pl = tid & 1;
        const __nv_bfloat16* s = (pl ? Vl : Vh) + zb + (size_t)(kt * 128 + krow) * DK;
        const uint32_t d = smaddr(Vs + krow * KST + pl * 64);
        #pragma unroll
        for (int i = 0; i < 8; i++) cpa16(d + i * 16, s + i * 8);
    };

    if (tid < 64) { rsm[tid] = 0.0f; rsm2[tid] = 0.0f; }

    // ---- Q: hi to smem, lo staged then kept in registers ----
    issueQhi(); stageQlo(); CP_COMMIT();
    CP_WAIT(0); __syncthreads();
    uint32_t Alr[4][4];
    #pragma unroll
    for (int kk = 0; kk < 4; kk++)
        ldsm4(Alr[kk][0], Alr[kk][1], Alr[kk][2], Alr[kk][3],
              smaddr(&Vs[(wm + afr) * KST + kk * 16 + afc]));
    __syncthreads();   // Vs free

    float rp0 = 0.f, rp1 = 0.f;

    if (WRITE_E) {
        // ====== pass 1: 2-mma rowsums, distance-2 prefetch (3 buffers) ======
        __nv_bfloat16* kb[3] = { KB0, KB1, Vs };
        issueKhi(0, kb[0]); CP_COMMIT();
        issueKhi(1, kb[1]); CP_COMMIT();
        for (int kt = 0; kt < 16; kt++) {
            if (kt < 15) CP_WAIT(1); else CP_WAIT(0);
            __syncthreads();
            if (kt + 2 < 16) { issueKhi(kt + 2, kb[(kt + 2) % 3]); CP_COMMIT(); }
            const __nv_bfloat16* Kt = kb[kt % 3];
            float Sacc[8][4] = {};
            #pragma unroll
            for (int kk = 0; kk < 4; kk++) {
                uint32_t Ah[4];
                ldsm4(Ah[0], Ah[1], Ah[2], Ah[3],
                      smaddr(&Qs[(wm + afr) * QST + kk * 16 + afc]));
                #pragma unroll
                for (int g = 0; g < 4; g++) {
                    uint32_t Bh[4];
                    ldsm4(Bh[0], Bh[1], Bh[2], Bh[3],
                          smaddr(&Kt[(wn + g * 16 + bRow) * KST + kk * 16 + bc8]));
                    mma16816(Sacc[2 * g],     Ah,      Bh[0], Bh[1]);
                    mma16816(Sacc[2 * g],     Alr[kk], Bh[0], Bh[1]);
                    mma16816(Sacc[2 * g + 1], Ah,      Bh[2], Bh[3]);
                    mma16816(Sacc[2 * g + 1], Alr[kk], Bh[2], Bh[3]);
                }
            }
            #pragma unroll
            for (int nf = 0; nf < 8; nf++) {
                rp0 += __expf(Sacc[nf][0] * 0.125f) + __expf(Sacc[nf][1] * 0.125f);
                rp1 += __expf(Sacc[nf][2] * 0.125f) + __expf(Sacc[nf][3] * 0.125f);
            }
        }
        CP_WAIT(0);
        {
            float v0 = rp0, v1 = rp1;
            v0 += __shfl_xor_sync(0xffffffffu, v0, 1);
            v0 += __shfl_xor_sync(0xffffffffu, v0, 2);
            v1 += __shfl_xor_sync(0xffffffffu, v1, 1);
            v1 += __shfl_xor_sync(0xffffffffu, v1, 2);
            if ((l & 3) == 0) {
                atomicAdd(&rsm[wm + (l >> 2)], v0);
                atomicAdd(&rsm[wm + (l >> 2) + 8], v1);
            }
        }
        __syncthreads();
        if (tid < 64) rsm[tid] = 1.0f / rsm[tid];
        __syncthreads();
    }

    float inv0 = 1.0f, inv1 = 1.0f;
    if (WRITE_E) { inv0 = rsm[wm + (l >> 2)]; inv1 = rsm[wm + (l >> 2) + 8]; }
    rp0 = rp1 = 0.f;

    // ============ pass 2: full precision + PV ============
    float acc[8][4] = {};
    issueK(0, KB0); CP_COMMIT();
    for (int kt = 0; kt < 16; kt++) {
        CP_WAIT(0); __syncthreads();          // b1: K(kt) ready, PV(kt-1) done
        issueV(kt); CP_COMMIT();
        const __nv_bfloat16* Kt = (kt & 1) ? KB1 : KB0;

        float Sacc[8][4] = {};
        #pragma unroll
        for (int kk = 0; kk < 4; kk++) {
            uint32_t Ah[4];
            ldsm4(Ah[0], Ah[1], Ah[2], Ah[3],
                  smaddr(&Qs[(wm + afr) * QST + kk * 16 + afc]));
            #pragma unroll
            for (int g = 0; g < 4; g++) {
                uint32_t Bh[4], Bl[4];
                const int row = wn + g * 16 + bRow;
                ldsm4(Bh[0], Bh[1], Bh[2], Bh[3],
                      smaddr(&Kt[row * KST + kk * 16 + bc8]));
                ldsm4(Bl[0], Bl[1], Bl[2], Bl[3],
                      smaddr(&Kt[row * KST + 64 + kk * 16 + bc8]));
                #pragma unroll
                for (int sub = 0; sub < 2; sub++) {
                    float* c = Sacc[2 * g + sub];
                    mma16816(c, Ah,      Bh[2 * sub], Bh[2 * sub + 1]);
                    mma16816(c, Ah,      Bl[2 * sub], Bl[2 * sub + 1]);
                    mma16816(c, Alr[kk], Bh[2 * sub], Bh[2 * sub + 1]);
                }
            }
        }
        if (kt < 15) { issueK(kt + 1, (kt & 1) ? KB0 : KB1); CP_COMMIT(); }
        if (kt < 15) CP_WAIT(1); else CP_WAIT(0);   // b2: V(kt) ready (race fix)
        __syncthreads();

        // ---- exp interleaved with PV ----
        #pragma unroll
        for (int j = 0; j < 4; j++) {
            uint32_t Aph[4], Apl[4];
            #pragma unroll
            for (int t = 0; t < 2; t++) {
                float* c = Sacc[2 * j + t];
                float e0 = __expf(c[0] * 0.125f), e1 = __expf(c[1] * 0.125f);
                float e2 = __expf(c[2] * 0.125f), e3 = __expf(c[3] * 0.125f);
                if (WRITE_E) { e0 *= inv0; e1 *= inv0; e2 *= inv1; e3 *= inv1; }
                rp0 += e0 + e1; rp1 += e2 + e3;
                __nv_bfloat16 h0 = __float2bfloat16(e0), h1 = __float2bfloat16(e1);
                __nv_bfloat16 h2 = __float2bfloat16(e2), h3 = __float2bfloat16(e3);
                Aph[2 * t]     = packbf(__bfloat162float(h0), __bfloat162float(h1));
                Aph[2 * t + 1] = packbf(__bfloat162float(h2), __bfloat162float(h3));
                Apl[2 * t]     = packbf(e0 - __bfloat162float(h0), e1 - __bfloat162float(h1));
                Apl[2 * t + 1] = packbf(e2 - __bfloat162float(h2), e3 - __bfloat162float(h3));
                if (WRITE_E) {
                    const int grow = y0 + wm + (l >> 2);
                    const int gcol = kt * 128 + wn + (2 * j + t) * 8 + 2 * (l & 3);
                    *(float2*)&attn[((size_t)z * S + grow) * S + gcol] = make_float2(e0, e1);
                    *(float2*)&attn[((size_t)z * S + grow + 8) * S + gcol] = make_float2(e2, e3);
                }
            }
            #pragma unroll
            for (int g = 0; g < 4; g++) {
                uint32_t Vhf[4], Vlf[4];
                const int row = wn + j * 16 + vkr;
                ldsm4t(Vhf[0], Vhf[1], Vhf[2], Vhf[3],
                       smaddr(&Vs[row * KST + g * 16 + vnc]));
                ldsm4t(Vlf[0], Vlf[1], Vlf[2], Vlf[3],
                       smaddr(&Vs[row * KST + 64 + g * 16 + vnc]));
                #pragma unroll
                for (int sub = 0; sub < 2; sub++) {
                    float* c = acc[2 * g + sub];
                    mma16816(c, Aph, Vhf[2 * sub], Vhf[2 * sub + 1]);
                    mma16816(c, Aph, Vlf[2 * sub], Vlf[2 * sub + 1]);
                    mma16816(c, Apl, Vhf[2 * sub], Vhf[2 * sub + 1]);
                }
            }
        }
    }

    // ---- exact row sums of (pre-normalized) P -> rsm2 ----
    {
        float v0 = rp0, v1 = rp1;
        v0 += __shfl_xor_sync(0xffffffffu, v0, 1);
        v0 += __shfl_xor_sync(0xffffffffu, v0, 2);
        v1 += __shfl_xor_sync(0xffffffffu, v1, 1);
        v1 += __shfl_xor_sync(0xffffffffu, v1, 2);
        if ((l & 3) == 0) {
            atomicAdd(&rsm2[wm + (l >> 2)], v0);
            atomicAdd(&rsm2[wm + (l >> 2) + 8], v1);
        }
    }
    __syncthreads();
    if (tid < 64) rsm2[tid] = 1.0f / rsm2[tid];
    __syncthreads();

    // ---- pair-reduce ctx across the two k-half warps, exact scale, store ----
    const int er = l >> 2;
    if (w & 1) {
        #pragma unroll
        for (int nf = 0; nf < 8; nf++) {
            const int r = wm + er, c = nf * 8 + 2 * (l & 3);
            *(float2*)&rbuf[r * 66 + c] = make_float2(acc[nf][0], acc[nf][1]);
            *(float2*)&rbuf[(r + 8) * 66 + c] = make_float2(acc[nf][2], acc[nf][3]);
        }
    }
    __syncthreads();
    if (!(w & 1)) {
        const int r = wm + er;
        const float s0 = rsm2[r], s1 = rsm2[r + 8];
        #pragma unroll
        for (int nf = 0; nf < 8; nf++) {
            const int c = nf * 8 + 2 * (l & 3);
            float2 p0 = *(float2*)&rbuf[r * 66 + c];
            float2 p1 = *(float2*)&rbuf[(r + 8) * 66 + c];
            *(float2*)&ctx[((size_t)bz * S + y0 + r) * D + hz * 64 + c] =
                make_float2((acc[nf][0] + p0.x) * s0, (acc[nf][1] + p0.y) * s0);
            *(float2*)&ctx[((size_t)bz * S + y0 + r + 8) * D + hz * 64 + c] =
                make_float2((acc[nf][2] + p1.x) * s1, (acc[nf][3] + p1.y) * s1);
        }
    }
}

// ---------------------------------------------------------------------------
extern "C" void kernel_launch(void* const* d_in, const int* in_sizes, int n_in,
                              void* d_out, int out_size)
{
    const float* query = (const float*)d_in[0];
    const float* key_i = (const float*)d_in[1];
    const float* value = (const float*)d_in[2];
    const float* w_q   = (const float*)d_in[3];
    const float* w_k   = (const float*)d_in[4];
    const float* w_v   = (const float*)d_in[5];
    const float* w_o   = (const float*)d_in[6];
    float* out = (float*)d_out;

    __nv_bfloat16 *qh, *ql, *kh, *kl, *vh, *vl;
    float *cp;
    cudaGetSymbolAddress((void**)&qh, g_qh);
    cudaGetSymbolAddress((void**)&ql, g_ql);
    cudaGetSymbolAddress((void**)&kh, g_kh);
    cudaGetSymbolAddress((void**)&kl, g_kl);
    cudaGetSymbolAddress((void**)&vh, g_vh);
    cudaGetSymbolAddress((void**)&vl, g_vl);
    cudaGetSymbolAddress((void**)&cp, g_ctx);

    const bool want_attn = ((long long)out_size >= OUT_ELEMS + ATT_ELEMS);
    float* attn = want_attn ? (out + OUT_ELEMS) : nullptr;

    const dim3 tb(256);
    const dim3 gproj(D / 128, (BATCH * S) / 128, 1);

    gemm_nt_mma<1><<<gproj, tb>>>(query, w_q, nullptr, qh, ql, D, D, 1.0f);
    gemm_nt_mma<1><<<gproj, tb>>>(key_i, w_k, nullptr, kh, kl, D, D, 1.0f);
    gemm_nt_mma<1><<<gproj, tb>>>(value, w_v, nullptr, vh, vl, D, D, 1.0f);

    // fused attention: Q 64-row tiles, 2 CTAs/SM
    const int smem = (64 * QST + 3 * 128 * KST) * 2 + 128 * 4;   // 114176 B
    const dim3 gf(S / 64, BH);
    if (want_attn) {
        cudaFuncSetAttribute(fused_attn<true>,
                             cudaFuncAttributeMaxDynamicSharedMemorySize, smem);
        fused_attn<true><<<gf, tb, smem>>>(qh, ql, kh, kl, vh, vl, cp, attn);
    } else {
        cudaFuncSetAttribute(fused_attn<false>,
                             cudaFuncAttributeMaxDynamicSharedMemorySize, smem);
        fused_attn<false><<<gf, tb, smem>>>(qh, ql, kh, kl, vh, vl, cp, nullptr);
    }

    gemm_nt_mma<0><<<gproj, tb>>>(cp, w_o, out, nullptr, nullptr, D, D, 1.0f);
}

// round 10
// speedup vs baseline: 1.1603x; 1.0426x over previous
#include <cuda_runtime.h>
#include <cuda_bf16.h>
#include <stdint.h>

// ---------------------------------------------------------------------------
// MultiHeadSelfAttention: B=2, S=2048, D=1024, H=16, dk=64
// R9: tcgen05 unavailable (harness ptxas targets sm_103 w/o 'a'); optimize
//     within mma.sync: pre-split fp32->bf16 hi/lo convert kernel, dense GEMMs
//     become pure cp.async(4-stage)+ldmatrix+mma with 2 CTAs/SM, projections
//     merged into one launch. fused_attn = R7 (proven, rel_err 7.2e-5).
// ---------------------------------------------------------------------------

namespace {
constexpr int BATCH = 2, S = 2048, D = 1024, H = 16, DK = 64, BH = 32;
constexpr long long OUT_ELEMS = (long long)BATCH * S * D;          // 4,194,304
constexpr long long ATT_ELEMS = (long long)BH * S * (long long)S;  // 134,217,728
constexpr int QST = 72;     // fused: Q smem stride (hi plane) bf16
constexpr int KST = 136;    // fused: K/V smem stride bf16
constexpr int GST = 40;     // gemm smem stride bf16 (hi 0-15, lo 16-31, pad 8)
constexpr int NSTG = 4;     // gemm cp.async stages
constexpr int GSMEM = NSTG * 128 * GST * 2 * 2;   // 81920 B
}

// ---- scratch (allocation-free __device__ globals) ----
// pre-split bf16 hi/lo planes of inputs & weights
__device__ __nv_bfloat16 g_xqh[(size_t)BATCH * S * D], g_xql[(size_t)BATCH * S * D];
__device__ __nv_bfloat16 g_xkh[(size_t)BATCH * S * D], g_xkl[(size_t)BATCH * S * D];
__device__ __nv_bfloat16 g_xvh[(size_t)BATCH * S * D], g_xvl[(size_t)BATCH * S * D];
__device__ __nv_bfloat16 g_wqh[(size_t)D * D], g_wql[(size_t)D * D];
__device__ __nv_bfloat16 g_wkh[(size_t)D * D], g_wkl[(size_t)D * D];
__device__ __nv_bfloat16 g_wvh[(size_t)D * D], g_wvl[(size_t)D * D];
__device__ __nv_bfloat16 g_woh[(size_t)D * D], g_wol[(size_t)D * D];
__device__ __nv_bfloat16 g_cxh[(size_t)BATCH * S * D], g_cxl[(size_t)BATCH * S * D];
// projected q/k/v planes (head-major [B,H,S,DK]) + fp32 ctx
__device__ __nv_bfloat16 g_qh[(size_t)BH * S * DK], g_ql[(size_t)BH * S * DK];
__device__ __nv_bfloat16 g_kh[(size_t)BH * S * DK], g_kl[(size_t)BH * S * DK];
__device__ __nv_bfloat16 g_vh[(size_t)BH * S * DK], g_vl[(size_t)BH * S * DK];
__device__ float g_ctx[(size_t)BATCH * S * D];

// ------------------------------ PTX helpers --------------------------------
__device__ __forceinline__ uint32_t smaddr(const void* p) {
    return (uint32_t)__cvta_generic_to_shared(p);
}
__device__ __forceinline__ void ldsm4(uint32_t& r0, uint32_t& r1, uint32_t& r2,
                                      uint32_t& r3, uint32_t a) {
    asm volatile("ldmatrix.sync.aligned.m8n8.x4.shared.b16 {%0,%1,%2,%3}, [%4];"
                 : "=r"(r0), "=r"(r1), "=r"(r2), "=r"(r3) : "r"(a));
}
__device__ __forceinline__ void ldsm4t(uint32_t& r0, uint32_t& r1, uint32_t& r2,
                                       uint32_t& r3, uint32_t a) {
    asm volatile("ldmatrix.sync.aligned.m8n8.x4.trans.shared.b16 {%0,%1,%2,%3}, [%4];"
                 : "=r"(r0), "=r"(r1), "=r"(r2), "=r"(r3) : "r"(a));
}
__device__ __forceinline__ void mma16816(float* c, const uint32_t* a,
                                         uint32_t b0, uint32_t b1) {
    asm volatile("mma.sync.aligned.m16n8k16.row.col.f32.bf16.bf16.f32 "
                 "{%0,%1,%2,%3}, {%4,%5,%6,%7}, {%8,%9}, {%0,%1,%2,%3};"
                 : "+f"(c[0]), "+f"(c[1]), "+f"(c[2]), "+f"(c[3])
                 : "r"(a[0]), "r"(a[1]), "r"(a[2]), "r"(a[3]), "r"(b0), "r"(b1));
}
__device__ __forceinline__ uint32_t packbf(float a, float b) {
    __nv_bfloat162 t = __halves2bfloat162(__float2bfloat16(a), __float2bfloat16(b));
    return *reinterpret_cast<uint32_t*>(&t);
}
__device__ __forceinline__ void cpa16(uint32_t dst, const void* src) {
    asm volatile("cp.async.cg.shared.global [%0], [%1], 16;" :: "r"(dst), "l"(src));
}
#define CP_COMMIT() asm volatile("cp.async.commit_group;")
#define CP_WAIT(N)  asm volatile("cp.async.wait_group %0;" :: "n"(N))

// fp32 float4 -> (4x bf16 hi, 4x bf16 lo) packed as uint2 each
__device__ __forceinline__ void split4(const float4 f, uint2& hi, uint2& lo) {
    __nv_bfloat16 hx = __float2bfloat16(f.x), hy = __float2bfloat16(f.y);
    __nv_bfloat16 hz = __float2bfloat16(f.z), hw = __float2bfloat16(f.w);
    __nv_bfloat16 lx = __float2bfloat16(f.x - __bfloat162float(hx));
    __nv_bfloat16 ly = __float2bfloat16(f.y - __bfloat162float(hy));
    __nv_bfloat16 lz = __float2bfloat16(f.z - __bfloat162float(hz));
    __nv_bfloat16 lw = __float2bfloat16(f.w - __bfloat162float(hw));
    __nv_bfloat162 h01 = __halves2bfloat162(hx, hy), h23 = __halves2bfloat162(hz, hw);
    __nv_bfloat162 l01 = __halves2bfloat162(lx, ly), l23 = __halves2bfloat162(lz, lw);
    hi.x = *reinterpret_cast<uint32_t*>(&h01); hi.y = *reinterpret_cast<uint32_t*>(&h23);
    lo.x = *reinterpret_cast<uint32_t*>(&l01); lo.y = *reinterpret_cast<uint32_t*>(&l23);
}

// ---------------------------------------------------------------------------
// Elementwise fp32 -> bf16 hi/lo plane split. grid.z selects tensor.
// ---------------------------------------------------------------------------
struct ConvArgs {
    const float* src[8];
    __nv_bfloat16* hi[8];
    __nv_bfloat16* lo[8];
    int n4[8];    // element count / 4
};

__global__ void __launch_bounds__(256)
convert_split(ConvArgs a)
{
    const int z = blockIdx.z;
    const int idx = blockIdx.x * 256 + threadIdx.x;
    if (idx >= a.n4[z]) return;
    float4 f = ((const float4*)a.src[z])[idx];
    uint2 hi, lo;
    split4(f, hi, lo);
    ((uint2*)a.hi[z])[idx] = hi;
    ((uint2*)a.lo[z])[idx] = lo;
}

// ---------------------------------------------------------------------------
// Dense NT GEMM from pre-split bf16 hi/lo planes. C = A @ B^T, M=4096,
// N=K=1024. 128x128 CTA tile, BK=16, 4-stage cp.async, 8 warps (64x32 warp
// tiles), 3-term hi/lo mma. EPI=1: bf16 hi/lo planes head-major [B,H,S,DK];
// EPI=0: fp32 C row-major. grid.z selects (A,B,C) set.
// ---------------------------------------------------------------------------
struct GemmArgs {
    const __nv_bfloat16 *ah[3], *al[3], *bh[3], *bl[3];
    float* c;
    __nv_bfloat16 *chi[3], *clo[3];
};

template <int EPI>
__global__ void __launch_bounds__(256, 2)
gemm_bf16(GemmArgs ga)
{
    constexpr int K = 1024;
    extern __shared__ __align__(16) __nv_bfloat16 sm[];
    __nv_bfloat16* As = sm;                       // [NSTG][128][GST]
    __nv_bfloat16* Bs = sm + NSTG * 128 * GST;

    const int zi = blockIdx.z;
    const __nv_bfloat16* Ah = ga.ah[zi];
    const __nv_bfloat16* Al = ga.al[zi];
    const __nv_bfloat16* Bh = ga.bh[zi];
    const __nv_bfloat16* Bl = ga.bl[zi];

    const int tid = threadIdx.x, w = tid >> 5, l = tid & 31;
    const int m0 = blockIdx.y * 128, n0 = blockIdx.x * 128;
    const int wm = (w >> 2) * 64, wn = (w & 3) * 32;

    // loader: row = tid&127, plane = tid>>7 (0:hi 1:lo); 2 chunks per tensor
    const int lrow = tid & 127, lpl = tid >> 7;
    const __nv_bfloat16* srcA = (lpl ? Al : Ah) + (size_t)(m0 + lrow) * K;
    const __nv_bfloat16* srcB = (lpl ? Bl : Bh) + (size_t)(n0 + lrow) * K;

    auto issue = [&](int kt) {
        const int stg = kt & (NSTG - 1);
        const uint32_t da = smaddr(As + (stg * 128 + lrow) * GST + lpl * 16);
        const __nv_bfloat16* sa = srcA + kt * 16;
        cpa16(da, sa); cpa16(da + 16, sa + 8);
        const uint32_t db = smaddr(Bs + (stg * 128 + lrow) * GST + lpl * 16);
        const __nv_bfloat16* sb = srcB + kt * 16;
        cpa16(db, sb); cpa16(db + 16, sb + 8);
        CP_COMMIT();
    };

    // fragment addresses (proven R2 mapping)
    const int afr = wm + (l & 15);
    const int afc = (l >> 4) * 8;
    const int bg  = l >> 3;
    const int bfr = wn + ((bg >> 1) << 3) + (l & 7);
    const int bfc = (bg & 1) * 8;

    issue(0); issue(1); issue(2);

    float acc[4][4][4] = {};
    const int KT = K / 16;   // 64
    for (int kt = 0; kt < KT; kt++) {
        CP_WAIT(2);
        __syncthreads();
        if (kt + 3 < KT) issue(kt + 3);

        const __nv_bfloat16* AsT = As + (kt & (NSTG - 1)) * 128 * GST;
        const __nv_bfloat16* BsT = Bs + (kt & (NSTG - 1)) * 128 * GST;

        uint32_t Bhf[8], Blf[8];
        ldsm4(Bhf[0], Bhf[1], Bhf[2], Bhf[3], smaddr(&BsT[bfr * GST + bfc]));
        ldsm4(Bhf[4], Bhf[5], Bhf[6], Bhf[7], smaddr(&BsT[(bfr + 16) * GST + bfc]));
        ldsm4(Blf[0], Blf[1], Blf[2], Blf[3], smaddr(&BsT[bfr * GST + bfc + 16]));
        ldsm4(Blf[4], Blf[5], Blf[6], Blf[7], smaddr(&BsT[(bfr + 16) * GST + bfc + 16]));

        #pragma unroll
        for (int mf = 0; mf < 4; mf++) {
            uint32_t Ahf[4], Alf[4];
            ldsm4(Ahf[0], Ahf[1], Ahf[2], Ahf[3],
                  smaddr(&AsT[(afr + mf * 16) * GST + afc]));
            ldsm4(Alf[0], Alf[1], Alf[2], Alf[3],
                  smaddr(&AsT[(afr + mf * 16) * GST + afc + 16]));
            #pragma unroll
            for (int nf = 0; nf < 4; nf++) {
                float* c = acc[mf][nf];
                mma16816(c, Ahf, Bhf[nf * 2], Bhf[nf * 2 + 1]);
                mma16816(c, Ahf, Blf[nf * 2], Blf[nf * 2 + 1]);
                mma16816(c, Alf, Bhf[nf * 2], Bhf[nf * 2 + 1]);
            }
        }
    }

    const int er = l >> 2, ec = (l & 3) * 2;
    #pragma unroll
    for (int mf = 0; mf < 4; mf++) {
        #pragma unroll
        for (int nf = 0; nf < 4; nf++) {
            const float* c = acc[mf][nf];
            const int rr = m0 + wm + mf * 16 + er;
            const int cc = n0 + wn + nf * 8 + ec;
            if (EPI == 1) {
                const int hh = cc >> 6, dd = cc & 63;
                const int bb = rr >> 11, ss = rr & (S - 1);
                const int rr2 = rr + 8, bb2 = rr2 >> 11, ss2 = rr2 & (S - 1);
                const size_t i0 = (((size_t)bb  * H + hh) * S + ss)  * DK + dd;
                const size_t i1 = (((size_t)bb2 * H + hh) * S + ss2) * DK + dd;
                __nv_bfloat16 h0 = __float2bfloat16(c[0]), h1 = __float2bfloat16(c[1]);
                __nv_bfloat16 h2 = __float2bfloat16(c[2]), h3 = __float2bfloat16(c[3]);
                *(uint32_t*)&ga.chi[zi][i0] = packbf(__bfloat162float(h0),
                                                     __bfloat162float(h1));
                *(uint32_t*)&ga.clo[zi][i0] = packbf(c[0] - __bfloat162float(h0),
                                                     c[1] - __bfloat162float(h1));
                *(uint32_t*)&ga.chi[zi][i1] = packbf(__bfloat162float(h2),
                                                     __bfloat162float(h3));
                *(uint32_t*)&ga.clo[zi][i1] = packbf(c[2] - __bfloat162float(h2),
                                                     c[3] - __bfloat162float(h3));
            } else {
                *(float2*)&ga.c[(size_t)rr * 1024 + cc] = make_float2(c[0], c[1]);
                *(float2*)&ga.c[(size_t)(rr + 8) * 1024 + cc] = make_float2(c[2], c[3]);
            }
        }
    }
}

// ---------------------------------------------------------------------------
// Fused attention (R7, proven: rel_err 7.2e-5). Grid (S/64, BH); 256 thr;
// 2 CTAs/SM. Warp tile 16(m) x 64(n k-half).
// ---------------------------------------------------------------------------
template <bool WRITE_E>
__global__ void __launch_bounds__(256, 2)
fused_attn(const __nv_bfloat16* __restrict__ Qh, const __nv_bfloat16* __restrict__ Ql,
           const __nv_bfloat16* __restrict__ Kh, const __nv_bfloat16* __restrict__ Kl,
           const __nv_bfloat16* __restrict__ Vh, const __nv_bfloat16* __restrict__ Vl,
           float* __restrict__ ctx, float* __restrict__ attn)
{
    extern __shared__ __align__(16) char smc[];
    __nv_bfloat16* Qs  = (__nv_bfloat16*)smc;
    __nv_bfloat16* KB0 = Qs + 64 * QST;
    __nv_bfloat16* KB1 = KB0 + 128 * KST;
    __nv_bfloat16* Vs  = KB1 + 128 * KST;
    float* rsm  = (float*)(Vs + 128 * KST);
    float* rsm2 = rsm + 64;
    float* rbuf = (float*)KB0;

    const int z = blockIdx.y, y0 = blockIdx.x * 64;
    const int bz = z >> 4, hz = z & 15;
    const size_t zb = (size_t)z * S * DK;

    const int tid = threadIdx.x, w = tid >> 5, l = tid & 31;
    const int wm = (w >> 1) * 16, wn = (w & 1) * 64;

    const int afr = (l & 15), afc = (l >> 4) * 8;
    const int bg = l >> 3, bRow = ((bg >> 1) << 3) + (l & 7), bc8 = (bg & 1) * 8;
    const int vkr = ((l >> 3) & 1) * 8 + (l & 7), vnc = (l >> 4) * 8;

    const int qrow = tid >> 2, qc = (tid & 3) * 16;
    auto issueQhi = [&]() {
        const __nv_bfloat16* s = Qh + zb + (size_t)(y0 + qrow) * DK + qc;
        const uint32_t d = smaddr(Qs + qrow * QST + qc);
        cpa16(d, s); cpa16(d + 16, s + 8);
    };
    auto stageQlo = [&]() {
        const __nv_bfloat16* s = Ql + zb + (size_t)(y0 + qrow) * DK + qc;
        const uint32_t d = smaddr(Vs + qrow * KST + qc);
        cpa16(d, s); cpa16(d + 16, s + 8);
    };
    const int krow = tid >> 1;
    auto issueK = [&](int kt, __nv_bfloat16* dst) {
        const int pl = tid & 1;
        const __nv_bfloat16* s = (pl ? Kl : Kh) + zb + (size_t)(kt * 128 + krow) * DK;
        const uint32_t d = smaddr(dst + krow * KST + pl * 64);
        #pragma unroll
        for (int i = 0; i < 8; i++) cpa16(d + i * 16, s + i * 8);
    };
    auto issueKhi = [&](int kt, __nv_bfloat16* dst) {
        const int hf = tid & 1;
        const __nv_bfloat16* s = Kh + zb + (size_t)(kt * 128 + krow) * DK + hf * 32;
        const uint32_t d = smaddr(dst + krow * KST + hf * 32);
        #pragma unroll
        for (int i = 0; i < 4; i++) cpa16(d + i * 16, s + i * 8);
    };
    auto issueV = [&](int kt) {
        const int pl = tid & 1;
        const __nv_bfloat16* s = (pl ? Vl : Vh) + zb + (size_t)(kt * 128 + krow) * DK;
        const uint32_t d = smaddr(Vs + krow * KST + pl * 64);
        #pragma unroll
        for (int i = 0; i < 8; i++) cpa16(d + i * 16, s + i * 8);
    };

    if (tid < 64) { rsm[tid] = 0.0f; rsm2[tid] = 0.0f; }

    issueQhi(); stageQlo(); CP_COMMIT();
    CP_WAIT(0); __syncthreads();
    uint32_t Alr[4][4];
    #pragma unroll
    for (int kk = 0; kk < 4; kk++)
        ldsm4(Alr[kk][0], Alr[kk][1], Alr[kk][2], Alr[kk][3],
              smaddr(&Vs[(wm + afr) * KST + kk * 16 + afc]));
    __syncthreads();

    float rp0 = 0.f, rp1 = 0.f;

    if (WRITE_E) {
        __nv_bfloat16* kb[3] = { KB0, KB1, Vs };
        issueKhi(0, kb[0]); CP_COMMIT();
        issueKhi(1, kb[1]); CP_COMMIT();
        for (int kt = 0; kt < 16; kt++) {
            if (kt < 15) CP_WAIT(1); else CP_WAIT(0);
            __syncthreads();
            if (kt + 2 < 16) { issueKhi(kt + 2, kb[(kt + 2) % 3]); CP_COMMIT(); }
            const __nv_bfloat16* Kt = kb[kt % 3];
            float Sacc[8][4] = {};
            #pragma unroll
            for (int kk = 0; kk < 4; kk++) {
                uint32_t Ah[4];
                ldsm4(Ah[0], Ah[1], Ah[2], Ah[3],
                      smaddr(&Qs[(wm + afr) * QST + kk * 16 + afc]));
                #pragma unroll
                for (int g = 0; g < 4; g++) {
                    uint32_t Bh[4];
                    ldsm4(Bh[0], Bh[1], Bh[2], Bh[3],
                          smaddr(&Kt[(wn + g * 16 + bRow) * KST + kk * 16 + bc8]));
                    mma16816(Sacc[2 * g],     Ah,      Bh[0], Bh[1]);
                    mma16816(Sacc[2 * g],     Alr[kk], Bh[0], Bh[1]);
                    mma16816(Sacc[2 * g + 1], Ah,      Bh[2], Bh[3]);
                    mma16816(Sacc[2 * g + 1], Alr[kk], Bh[2], Bh[3]);
                }
            }
            #pragma unroll
            for (int nf = 0; nf < 8; nf++) {
                rp0 += __expf(Sacc[nf][0] * 0.125f) + __expf(Sacc[nf][1] * 0.125f);
                rp1 += __expf(Sacc[nf][2] * 0.125f) + __expf(Sacc[nf][3] * 0.125f);
            }
        }
        CP_WAIT(0);
        {
            float v0 = rp0, v1 = rp1;
            v0 += __shfl_xor_sync(0xffffffffu, v0, 1);
            v0 += __shfl_xor_sync(0xffffffffu, v0, 2);
            v1 += __shfl_xor_sync(0xffffffffu, v1, 1);
            v1 += __shfl_xor_sync(0xffffffffu, v1, 2);
            if ((l & 3) == 0) {
                atomicAdd(&rsm[wm + (l >> 2)], v0);
                atomicAdd(&rsm[wm + (l >> 2) + 8], v1);
            }
        }
        __syncthreads();
        if (tid < 64) rsm[tid] = 1.0f / rsm[tid];
        __syncthreads();
    }

    float inv0 = 1.0f, inv1 = 1.0f;
    if (WRITE_E) { inv0 = rsm[wm + (l >> 2)]; inv1 = rsm[wm + (l >> 2) + 8]; }
    rp0 = rp1 = 0.f;

    float acc[8][4] = {};
    issueK(0, KB0); CP_COMMIT();
    for (int kt = 0; kt < 16; kt++) {
        CP_WAIT(0); __syncthreads();
        issueV(kt); CP_COMMIT();
        const __nv_bfloat16* Kt = (kt & 1) ? KB1 : KB0;

        float Sacc[8][4] = {};
        #pragma unroll
        for (int kk = 0; kk < 4; kk++) {
            uint32_t Ah[4];
            ldsm4(Ah[0], Ah[1], Ah[2], Ah[3],
                  smaddr(&Qs[(wm + afr) * QST + kk * 16 + afc]));
            #pragma unroll
            for (int g = 0; g < 4; g++) {
                uint32_t Bh[4], Bl[4];
                const int row = wn + g * 16 + bRow;
                ldsm4(Bh[0], Bh[1], Bh[2], Bh[3],
                      smaddr(&Kt[row * KST + kk * 16 + bc8]));
                ldsm4(Bl[0], Bl[1], Bl[2], Bl[3],
                      smaddr(&Kt[row * KST + 64 + kk * 16 + bc8]));
                #pragma unroll
                for (int sub = 0; sub < 2; sub++) {
                    float* c = Sacc[2 * g + sub];
                    mma16816(c, Ah,      Bh[2 * sub], Bh[2 * sub + 1]);
                    mma16816(c, Ah,      Bl[2 * sub], Bl[2 * sub + 1]);
                    mma16816(c, Alr[kk], Bh[2 * sub], Bh[2 * sub + 1]);
                }
            }
        }
        if (kt < 15) { issueK(kt + 1, (kt & 1) ? KB0 : KB1); CP_COMMIT(); }
        if (kt < 15) CP_WAIT(1); else CP_WAIT(0);
        __syncthreads();

        #pragma unroll
        for (int j = 0; j < 4; j++) {
            uint32_t Aph[4], Apl[4];
            #pragma unroll
            for (int t = 0; t < 2; t++) {
                float* c = Sacc[2 * j + t];
                float e0 = __expf(c[0] * 0.125f), e1 = __expf(c[1] * 0.125f);
                float e2 = __expf(c[2] * 0.125f), e3 = __expf(c[3] * 0.125f);
                if (WRITE_E) { e0 *= inv0; e1 *= inv0; e2 *= inv1; e3 *= inv1; }
                rp0 += e0 + e1; rp1 += e2 + e3;
                __nv_bfloat16 h0 = __float2bfloat16(e0), h1 = __float2bfloat16(e1);
                __nv_bfloat16 h2 = __float2bfloat16(e2), h3 = __float2bfloat16(e3);
                Aph[2 * t]     = packbf(__bfloat162float(h0), __bfloat162float(h1));
                Aph[2 * t + 1] = packbf(__bfloat162float(h2), __bfloat162float(h3));
                Apl[2 * t]     = packbf(e0 - __bfloat162float(h0), e1 - __bfloat162float(h1));
                Apl[2 * t + 1] = packbf(e2 - __bfloat162float(h2), e3 - __bfloat162float(h3));
                if (WRITE_E) {
                    const int grow = y0 + wm + (l >> 2);
                    const int gcol = kt * 128 + wn + (2 * j + t) * 8 + 2 * (l & 3);
                    *(float2*)&attn[((size_t)z * S + grow) * S + gcol] = make_float2(e0, e1);
                    *(float2*)&attn[((size_t)z * S + grow + 8) * S + gcol] = make_float2(e2, e3);
                }
            }
            #pragma unroll
            for (int g = 0; g < 4; g++) {
                uint32_t Vhf[4], Vlf[4];
                const int row = wn + j * 16 + vkr;
                ldsm4t(Vhf[0], Vhf[1], Vhf[2], Vhf[3],
                       smaddr(&Vs[row * KST + g * 16 + vnc]));
                ldsm4t(Vlf[0], Vlf[1], Vlf[2], Vlf[3],
                       smaddr(&Vs[row * KST + 64 + g * 16 + vnc]));
                #pragma unroll
                for (int sub = 0; sub < 2; sub++) {
                    float* c = acc[2 * g + sub];
                    mma16816(c, Aph, Vhf[2 * sub], Vhf[2 * sub + 1]);
                    mma16816(c, Aph, Vlf[2 * sub], Vlf[2 * sub + 1]);
                    mma16816(c, Apl, Vhf[2 * sub], Vhf[2 * sub + 1]);
                }
            }
        }
    }

    {
        float v0 = rp0, v1 = rp1;
        v0 += __shfl_xor_sync(0xffffffffu, v0, 1);
        v0 += __shfl_xor_sync(0xffffffffu, v0, 2);
        v1 += __shfl_xor_sync(0xffffffffu, v1, 1);
        v1 += __shfl_xor_sync(0xffffffffu, v1, 2);
        if ((l & 3) == 0) {
            atomicAdd(&rsm2[wm + (l >> 2)], v0);
            atomicAdd(&rsm2[wm + (l >> 2) + 8], v1);
        }
    }
    __syncthreads();
    if (tid < 64) rsm2[tid] = 1.0f / rsm2[tid];
    __syncthreads();

    const int er = l >> 2;
    if (w & 1) {
        #pragma unroll
        for (int nf = 0; nf < 8; nf++) {
            const int r = wm + er, c = nf * 8 + 2 * (l & 3);
            *(float2*)&rbuf[r * 66 + c] = make_float2(acc[nf][0], acc[nf][1]);
            *(float2*)&rbuf[(r + 8) * 66 + c] = make_float2(acc[nf][2], acc[nf][3]);
        }
    }
    __syncthreads();
    if (!(w & 1)) {
        const int r = wm + er;
        const float s0 = rsm2[r], s1 = rsm2[r + 8];
        #pragma unroll
        for (int nf = 0; nf < 8; nf++) {
            const int c = nf * 8 + 2 * (l & 3);
            float2 p0 = *(float2*)&rbuf[r * 66 + c];
            float2 p1 = *(float2*)&rbuf[(r + 8) * 66 + c];
            *(float2*)&ctx[((size_t)bz * S + y0 + r) * D + hz * 64 + c] =
                make_float2((acc[nf][0] + p0.x) * s0, (acc[nf][1] + p0.y) * s0);
            *(float2*)&ctx[((size_t)bz * S + y0 + r + 8) * D + hz * 64 + c] =
                make_float2((acc[nf][2] + p1.x) * s1, (acc[nf][3] + p1.y) * s1);
        }
    }
}

// ---------------------------------------------------------------------------
extern "C" void kernel_launch(void* const* d_in, const int* in_sizes, int n_in,
                              void* d_out, int out_size)
{
    const float* query = (const float*)d_in[0];
    const float* key_i = (const float*)d_in[1];
    const float* value = (const float*)d_in[2];
    const float* w_q   = (const float*)d_in[3];
    const float* w_k   = (const float*)d_in[4];
    const float* w_v   = (const float*)d_in[5];
    const float* w_o   = (const float*)d_in[6];
    float* out = (float*)d_out;

    __nv_bfloat16 *xqh, *xql, *xkh, *xkl, *xvh, *xvl;
    __nv_bfloat16 *wqh, *wql, *wkh, *wkl, *wvh, *wvl, *woh, *wol;
    __nv_bfloat16 *cxh, *cxl;
    __nv_bfloat16 *qh, *ql, *kh, *kl, *vh, *vl;
    float *cp;
    cudaGetSymbolAddress((void**)&xqh, g_xqh); cudaGetSymbolAddress((void**)&xql, g_xql);
    cudaGetSymbolAddress((void**)&xkh, g_xkh); cudaGetSymbolAddress((void**)&xkl, g_xkl);
    cudaGetSymbolAddress((void**)&xvh, g_xvh); cudaGetSymbolAddress((void**)&xvl, g_xvl);
    cudaGetSymbolAddress((void**)&wqh, g_wqh); cudaGetSymbolAddress((void**)&wql, g_wql);
    cudaGetSymbolAddress((void**)&wkh, g_wkh); cudaGetSymbolAddress((void**)&wkl, g_wkl);
    cudaGetSymbolAddress((void**)&wvh, g_wvh); cudaGetSymbolAddress((void**)&wvl, g_wvl);
    cudaGetSymbolAddress((void**)&woh, g_woh); cudaGetSymbolAddress((void**)&wol, g_wol);
    cudaGetSymbolAddress((void**)&cxh, g_cxh); cudaGetSymbolAddress((void**)&cxl, g_cxl);
    cudaGetSymbolAddress((void**)&qh, g_qh);   cudaGetSymbolAddress((void**)&ql, g_ql);
    cudaGetSymbolAddress((void**)&kh, g_kh);   cudaGetSymbolAddress((void**)&kl, g_kl);
    cudaGetSymbolAddress((void**)&vh, g_vh);   cudaGetSymbolAddress((void**)&vl, g_vl);
    cudaGetSymbolAddress((void**)&cp, g_ctx);

    const bool want_attn = ((long long)out_size >= OUT_ELEMS + ATT_ELEMS);
    float* attn = want_attn ? (out + OUT_ELEMS) : nullptr;

    // ---- 1. split all fp32 inputs/weights into bf16 hi/lo planes ----
    ConvArgs ca{};
    ca.src[0] = query; ca.hi[0] = xqh; ca.lo[0] = xql; ca.n4[0] = (int)(OUT_ELEMS / 4);
    ca.src[1] = key_i; ca.hi[1] = xkh; ca.lo[1] = xkl; ca.n4[1] = (int)(OUT_ELEMS / 4);
    ca.src[2] = value; ca.hi[2] = xvh; ca.lo[2] = xvl; ca.n4[2] = (int)(OUT_ELEMS / 4);
    ca.src[3] = w_q;   ca.hi[3] = wqh; ca.lo[3] = wql; ca.n4[3] = D * D / 4;
    ca.src[4] = w_k;   ca.hi[4] = wkh; ca.lo[4] = wkl; ca.n4[4] = D * D / 4;
    ca.src[5] = w_v;   ca.hi[5] = wvh; ca.lo[5] = wvl; ca.n4[5] = D * D / 4;
    ca.src[6] = w_o;   ca.hi[6] = woh; ca.lo[6] = wol; ca.n4[6] = D * D / 4;
    convert_split<<<dim3((unsigned)(OUT_ELEMS / 4 / 256), 1, 7), 256>>>(ca);

    cudaFuncSetAttribute(gemm_bf16<1>, cudaFuncAttributeMaxDynamicSharedMemorySize, GSMEM);
    cudaFuncSetAttribute(gemm_bf16<0>, cudaFuncAttributeMaxDynamicSharedMemorySize, GSMEM);

    // ---- 2. q/k/v projections (one launch, grid.z=3) ----
    GemmArgs gp{};
    gp.ah[0] = xqh; gp.al[0] = xql; gp.bh[0] = wqh; gp.bl[0] = wql;
    gp.ah[1] = xkh; gp.al[1] = xkl; gp.bh[1] = wkh; gp.bl[1] = wkl;
    gp.ah[2] = xvh; gp.al[2] = xvl; gp.bh[2] = wvh; gp.bl[2] = wvl;
    gp.chi[0] = qh; gp.clo[0] = ql;
    gp.chi[1] = kh; gp.clo[1] = kl;
    gp.chi[2] = vh; gp.clo[2] = vl;
    gemm_bf16<1><<<dim3(8, 32, 3), 256, GSMEM>>>(gp);

    // ---- 3. fused attention ----
    const int smem = (64 * QST + 3 * 128 * KST) * 2 + 128 * 4;   // 114176 B
    const dim3 gf(S / 64, BH);
    if (want_attn) {
        cudaFuncSetAttribute(fused_attn<true>,
                             cudaFuncAttributeMaxDynamicSharedMemorySize, smem);
        fused_attn<true><<<gf, dim3(256), smem>>>(qh, ql, kh, kl, vh, vl, cp, attn);
    } else {
        cudaFuncSetAttribute(fused_attn<false>,
                             cudaFuncAttributeMaxDynamicSharedMemorySize, smem);
        fused_attn<false><<<gf, dim3(256), smem>>>(qh, ql, kh, kl, vh, vl, cp, nullptr);
    }

    // ---- 4. split ctx, 5. out = ctx @ Wo^T ----
    ConvArgs cc{};
    cc.src[0] = cp; cc.hi[0] = cxh; cc.lo[0] = cxl; cc.n4[0] = (int)(OUT_ELEMS / 4);
    convert_split<<<dim3((unsigned)(OUT_ELEMS / 4 / 256), 1, 1), 256>>>(cc);

    GemmArgs go{};
    go.ah[0] = cxh; go.al[0] = cxl; go.bh[0] = woh; go.bl[0] = wol;
    go.c = out;
    gemm_bf16<0><<<dim3(8, 32, 1), 256, GSMEM>>>(go);
}

// round 11
// speedup vs baseline: 1.1845x; 1.0208x over previous
#include <cuda_runtime.h>
#include <cuda_bf16.h>
#include <stdint.h>

// ---------------------------------------------------------------------------
// MultiHeadSelfAttention: B=2, S=2048, D=1024, H=16, dk=64
// R10: pass1 -> 1-mma rowsums (exact ctx norm makes this safe ~1.5e-4);
//      fused epilogue writes ctx as bf16 hi/lo planes (kills 2nd convert);
//      dense GEMM pipeline deepened to 5 cp.async stages.
// ---------------------------------------------------------------------------

namespace {
constexpr int BATCH = 2, S = 2048, D = 1024, H = 16, DK = 64, BH = 32;
constexpr long long OUT_ELEMS = (long long)BATCH * S * D;          // 4,194,304
constexpr long long ATT_ELEMS = (long long)BH * S * (long long)S;  // 134,217,728
constexpr int QST = 72;     // fused: Q smem stride (hi plane) bf16
constexpr int KST = 136;    // fused: K/V smem stride bf16
constexpr int GST = 40;     // gemm smem stride bf16 (hi 0-15, lo 16-31, pad 8)
constexpr int NSTG = 5;     // gemm cp.async stages
constexpr int GSMEM = NSTG * 128 * GST * 2 * 2;   // 102400 B
}

// ---- scratch (allocation-free __device__ globals) ----
__device__ __nv_bfloat16 g_xqh[(size_t)BATCH * S * D], g_xql[(size_t)BATCH * S * D];
__device__ __nv_bfloat16 g_xkh[(size_t)BATCH * S * D], g_xkl[(size_t)BATCH * S * D];
__device__ __nv_bfloat16 g_xvh[(size_t)BATCH * S * D], g_xvl[(size_t)BATCH * S * D];
__device__ __nv_bfloat16 g_wqh[(size_t)D * D], g_wql[(size_t)D * D];
__device__ __nv_bfloat16 g_wkh[(size_t)D * D], g_wkl[(size_t)D * D];
__device__ __nv_bfloat16 g_wvh[(size_t)D * D], g_wvl[(size_t)D * D];
__device__ __nv_bfloat16 g_woh[(size_t)D * D], g_wol[(size_t)D * D];
__device__ __nv_bfloat16 g_cxh[(size_t)BATCH * S * D], g_cxl[(size_t)BATCH * S * D];
__device__ __nv_bfloat16 g_qh[(size_t)BH * S * DK], g_ql[(size_t)BH * S * DK];
__device__ __nv_bfloat16 g_kh[(size_t)BH * S * DK], g_kl[(size_t)BH * S * DK];
__device__ __nv_bfloat16 g_vh[(size_t)BH * S * DK], g_vl[(size_t)BH * S * DK];

// ------------------------------ PTX helpers --------------------------------
__device__ __forceinline__ uint32_t smaddr(const void* p) {
    return (uint32_t)__cvta_generic_to_shared(p);
}
__device__ __forceinline__ void ldsm4(uint32_t& r0, uint32_t& r1, uint32_t& r2,
                                      uint32_t& r3, uint32_t a) {
    asm volatile("ldmatrix.sync.aligned.m8n8.x4.shared.b16 {%0,%1,%2,%3}, [%4];"
                 : "=r"(r0), "=r"(r1), "=r"(r2), "=r"(r3) : "r"(a));
}
__device__ __forceinline__ void ldsm4t(uint32_t& r0, uint32_t& r1, uint32_t& r2,
                                       uint32_t& r3, uint32_t a) {
    asm volatile("ldmatrix.sync.aligned.m8n8.x4.trans.shared.b16 {%0,%1,%2,%3}, [%4];"
                 : "=r"(r0), "=r"(r1), "=r"(r2), "=r"(r3) : "r"(a));
}
__device__ __forceinline__ void mma16816(float* c, const uint32_t* a,
                                         uint32_t b0, uint32_t b1) {
    asm volatile("mma.sync.aligned.m16n8k16.row.col.f32.bf16.bf16.f32 "
                 "{%0,%1,%2,%3}, {%4,%5,%6,%7}, {%8,%9}, {%0,%1,%2,%3};"
                 : "+f"(c[0]), "+f"(c[1]), "+f"(c[2]), "+f"(c[3])
                 : "r"(a[0]), "r"(a[1]), "r"(a[2]), "r"(a[3]), "r"(b0), "r"(b1));
}
__device__ __forceinline__ uint32_t packbf(float a, float b) {
    __nv_bfloat162 t = __halves2bfloat162(__float2bfloat16(a), __float2bfloat16(b));
    return *reinterpret_cast<uint32_t*>(&t);
}
__device__ __forceinline__ void cpa16(uint32_t dst, const void* src) {
    asm volatile("cp.async.cg.shared.global [%0], [%1], 16;" :: "r"(dst), "l"(src));
}
#define CP_COMMIT() asm volatile("cp.async.commit_group;")
#define CP_WAIT(N)  asm volatile("cp.async.wait_group %0;" :: "n"(N))

__device__ __forceinline__ void split4(const float4 f, uint2& hi, uint2& lo) {
    __nv_bfloat16 hx = __float2bfloat16(f.x), hy = __float2bfloat16(f.y);
    __nv_bfloat16 hz = __float2bfloat16(f.z), hw = __float2bfloat16(f.w);
    __nv_bfloat16 lx = __float2bfloat16(f.x - __bfloat162float(hx));
    __nv_bfloat16 ly = __float2bfloat16(f.y - __bfloat162float(hy));
    __nv_bfloat16 lz = __float2bfloat16(f.z - __bfloat162float(hz));
    __nv_bfloat16 lw = __float2bfloat16(f.w - __bfloat162float(hw));
    __nv_bfloat162 h01 = __halves2bfloat162(hx, hy), h23 = __halves2bfloat162(hz, hw);
    __nv_bfloat162 l01 = __halves2bfloat162(lx, ly), l23 = __halves2bfloat162(lz, lw);
    hi.x = *reinterpret_cast<uint32_t*>(&h01); hi.y = *reinterpret_cast<uint32_t*>(&h23);
    lo.x = *reinterpret_cast<uint32_t*>(&l01); lo.y = *reinterpret_cast<uint32_t*>(&l23);
}

// ---------------------------------------------------------------------------
// Elementwise fp32 -> bf16 hi/lo plane split. grid.z selects tensor.
// ---------------------------------------------------------------------------
struct ConvArgs {
    const float* src[8];
    __nv_bfloat16* hi[8];
    __nv_bfloat16* lo[8];
    int n4[8];
};

__global__ void __launch_bounds__(256)
convert_split(ConvArgs a)
{
    const int z = blockIdx.z;
    const int idx = blockIdx.x * 256 + threadIdx.x;
    if (idx >= a.n4[z]) return;
    float4 f = ((const float4*)a.src[z])[idx];
    uint2 hi, lo;
    split4(f, hi, lo);
    ((uint2*)a.hi[z])[idx] = hi;
    ((uint2*)a.lo[z])[idx] = lo;
}

// ---------------------------------------------------------------------------
// Dense NT GEMM from pre-split bf16 hi/lo planes. 128x128 CTA, BK=16,
// 5-stage cp.async, 8 warps (64x32 warp tiles), 3-term hi/lo mma.
// EPI=1: bf16 hi/lo planes head-major [B,H,S,DK]; EPI=0: fp32 C row-major.
// ---------------------------------------------------------------------------
struct GemmArgs {
    const __nv_bfloat16 *ah[3], *al[3], *bh[3], *bl[3];
    float* c;
    __nv_bfloat16 *chi[3], *clo[3];
};

template <int EPI>
__global__ void __launch_bounds__(256, 2)
gemm_bf16(GemmArgs ga)
{
    constexpr int K = 1024;
    extern __shared__ __align__(16) __nv_bfloat16 sm[];
    __nv_bfloat16* As = sm;                       // [NSTG][128][GST]
    __nv_bfloat16* Bs = sm + NSTG * 128 * GST;

    const int zi = blockIdx.z;
    const __nv_bfloat16* Ah = ga.ah[zi];
    const __nv_bfloat16* Al = ga.al[zi];
    const __nv_bfloat16* Bh = ga.bh[zi];
    const __nv_bfloat16* Bl = ga.bl[zi];

    const int tid = threadIdx.x, w = tid >> 5, l = tid & 31;
    const int m0 = blockIdx.y * 128, n0 = blockIdx.x * 128;
    const int wm = (w >> 2) * 64, wn = (w & 3) * 32;

    const int lrow = tid & 127, lpl = tid >> 7;
    const __nv_bfloat16* srcA = (lpl ? Al : Ah) + (size_t)(m0 + lrow) * K;
    const __nv_bfloat16* srcB = (lpl ? Bl : Bh) + (size_t)(n0 + lrow) * K;

    auto issue = [&](int kt, int stg) {
        const uint32_t da = smaddr(As + (stg * 128 + lrow) * GST + lpl * 16);
        const __nv_bfloat16* sa = srcA + kt * 16;
        cpa16(da, sa); cpa16(da + 16, sa + 8);
        const uint32_t db = smaddr(Bs + (stg * 128 + lrow) * GST + lpl * 16);
        const __nv_bfloat16* sb = srcB + kt * 16;
        cpa16(db, sb); cpa16(db + 16, sb + 8);
        CP_COMMIT();
    };

    const int afr = wm + (l & 15);
    const int afc = (l >> 4) * 8;
    const int bg  = l >> 3;
    const int bfr = wn + ((bg >> 1) << 3) + (l & 7);
    const int bfc = (bg & 1) * 8;

    issue(0, 0); issue(1, 1); issue(2, 2); issue(3, 3);

    float acc[4][4][4] = {};
    const int KT = K / 16;   // 64
    int stg = 0, pstg = 4;   // current stage, prefetch stage
    for (int kt = 0; kt < KT; kt++) {
        CP_WAIT(3);
        __syncthreads();
        if (kt + 4 < KT) {
            issue(kt + 4, pstg);
            if (++pstg == NSTG) pstg = 0;
        }

        const __nv_bfloat16* AsT = As + stg * 128 * GST;
        const __nv_bfloat16* BsT = Bs + stg * 128 * GST;
        if (++stg == NSTG) stg = 0;

        uint32_t Bhf[8], Blf[8];
        ldsm4(Bhf[0], Bhf[1], Bhf[2], Bhf[3], smaddr(&BsT[bfr * GST + bfc]));
        ldsm4(Bhf[4], Bhf[5], Bhf[6], Bhf[7], smaddr(&BsT[(bfr + 16) * GST + bfc]));
        ldsm4(Blf[0], Blf[1], Blf[2], Blf[3], smaddr(&BsT[bfr * GST + bfc + 16]));
        ldsm4(Blf[4], Blf[5], Blf[6], Blf[7], smaddr(&BsT[(bfr + 16) * GST + bfc + 16]));

        #pragma unroll
        for (int mf = 0; mf < 4; mf++) {
            uint32_t Ahf[4], Alf[4];
            ldsm4(Ahf[0], Ahf[1], Ahf[2], Ahf[3],
                  smaddr(&AsT[(afr + mf * 16) * GST + afc]));
            ldsm4(Alf[0], Alf[1], Alf[2], Alf[3],
                  smaddr(&AsT[(afr + mf * 16) * GST + afc + 16]));
            #pragma unroll
            for (int nf = 0; nf < 4; nf++) {
                float* c = acc[mf][nf];
                mma16816(c, Ahf, Bhf[nf * 2], Bhf[nf * 2 + 1]);
                mma16816(c, Ahf, Blf[nf * 2], Blf[nf * 2 + 1]);
                mma16816(c, Alf, Bhf[nf * 2], Bhf[nf * 2 + 1]);
            }
        }
    }

    const int er = l >> 2, ec = (l & 3) * 2;
    #pragma unroll
    for (int mf = 0; mf < 4; mf++) {
        #pragma unroll
        for (int nf = 0; nf < 4; nf++) {
            const float* c = acc[mf][nf];
            const int rr = m0 + wm + mf * 16 + er;
            const int cc = n0 + wn + nf * 8 + ec;
            if (EPI == 1) {
                const int hh = cc >> 6, dd = cc & 63;
                const int bb = rr >> 11, ss = rr & (S - 1);
                const int rr2 = rr + 8, bb2 = rr2 >> 11, ss2 = rr2 & (S - 1);
                const size_t i0 = (((size_t)bb  * H + hh) * S + ss)  * DK + dd;
                const size_t i1 = (((size_t)bb2 * H + hh) * S + ss2) * DK + dd;
                __nv_bfloat16 h0 = __float2bfloat16(c[0]), h1 = __float2bfloat16(c[1]);
                __nv_bfloat16 h2 = __float2bfloat16(c[2]), h3 = __float2bfloat16(c[3]);
                *(uint32_t*)&ga.chi[zi][i0] = packbf(__bfloat162float(h0),
                                                     __bfloat162float(h1));
                *(uint32_t*)&ga.clo[zi][i0] = packbf(c[0] - __bfloat162float(h0),
                                                     c[1] - __bfloat162float(h1));
                *(uint32_t*)&ga.chi[zi][i1] = packbf(__bfloat162float(h2),
                                                     __bfloat162float(h3));
                *(uint32_t*)&ga.clo[zi][i1] = packbf(c[2] - __bfloat162float(h2),
                                                     c[3] - __bfloat162float(h3));
            } else {
                *(float2*)&ga.c[(size_t)rr * 1024 + cc] = make_float2(c[0], c[1]);
                *(float2*)&ga.c[(size_t)(rr + 8) * 1024 + cc] = make_float2(c[2], c[3]);
            }
        }
    }
}

// ---------------------------------------------------------------------------
// Fused attention. Grid (S/64, BH); 256 thr; 2 CTAs/SM.
// Pass1: 1-mma (Qhi*Khi) rowsums. Pass2: full 3-term; ctx exactly normalized
// via in-pass sums (rsm2) and written directly as bf16 hi/lo planes.
// ---------------------------------------------------------------------------
template <bool WRITE_E>
__global__ void __launch_bounds__(256, 2)
fused_attn(const __nv_bfloat16* __restrict__ Qh, const __nv_bfloat16* __restrict__ Ql,
           const __nv_bfloat16* __restrict__ Kh, const __nv_bfloat16* __restrict__ Kl,
           const __nv_bfloat16* __restrict__ Vh, const __nv_bfloat16* __restrict__ Vl,
           __nv_bfloat16* __restrict__ cxh, __nv_bfloat16* __restrict__ cxl,
           float* __restrict__ attn)
{
    extern __shared__ __align__(16) char smc[];
    __nv_bfloat16* Qs  = (__nv_bfloat16*)smc;
    __nv_bfloat16* KB0 = Qs + 64 * QST;
    __nv_bfloat16* KB1 = KB0 + 128 * KST;
    __nv_bfloat16* Vs  = KB1 + 128 * KST;
    float* rsm  = (float*)(Vs + 128 * KST);
    float* rsm2 = rsm + 64;
    float* rbuf = (float*)KB0;

    const int z = blockIdx.y, y0 = blockIdx.x * 64;
    const int bz = z >> 4, hz = z & 15;
    const size_t zb = (size_t)z * S * DK;

    const int tid = threadIdx.x, w = tid >> 5, l = tid & 31;
    const int wm = (w >> 1) * 16, wn = (w & 1) * 64;

    const int afr = (l & 15), afc = (l >> 4) * 8;
    const int bg = l >> 3, bRow = ((bg >> 1) << 3) + (l & 7), bc8 = (bg & 1) * 8;
    const int vkr = ((l >> 3) & 1) * 8 + (l & 7), vnc = (l >> 4) * 8;

    const int qrow = tid >> 2, qc = (tid & 3) * 16;
    auto issueQhi = [&]() {
        const __nv_bfloat16* s = Qh + zb + (size_t)(y0 + qrow) * DK + qc;
        const uint32_t d = smaddr(Qs + qrow * QST + qc);
        cpa16(d, s); cpa16(d + 16, s + 8);
    };
    auto stageQlo = [&]() {
        const __nv_bfloat16* s = Ql + zb + (size_t)(y0 + qrow) * DK + qc;
        const uint32_t d = smaddr(Vs + qrow * KST + qc);
        cpa16(d, s); cpa16(d + 16, s + 8);
    };
    const int krow = tid >> 1;
    auto issueK = [&](int kt, __nv_bfloat16* dst) {
        const int pl = tid & 1;
        const __nv_bfloat16* s = (pl ? Kl : Kh) + zb + (size_t)(kt * 128 + krow) * DK;
        const uint32_t d = smaddr(dst + krow * KST + pl * 64);
        #pragma unroll
        for (int i = 0; i < 8; i++) cpa16(d + i * 16, s + i * 8);
    };
    auto issueKhi = [&](int kt, __nv_bfloat16* dst) {
        const int hf = tid & 1;
        const __nv_bfloat16* s = Kh + zb + (size_t)(kt * 128 + krow) * DK + hf * 32;
        const uint32_t d = smaddr(dst + krow * KST + hf * 32);
        #pragma unroll
        for (int i = 0; i < 4; i++) cpa16(d + i * 16, s + i * 8);
    };
    auto issueV = [&](int kt) {
        const int pl = tid & 1;
        const __nv_bfloat16* s = (pl ? Vl : Vh) + zb + (size_t)(kt * 128 + krow) * DK;
        const uint32_t d = smaddr(Vs + krow * KST + pl * 64);
        #pragma unroll
        for (int i = 0; i < 8; i++) cpa16(d + i * 16, s + i * 8);
    };

    if (tid < 64) { rsm[tid] = 0.0f; rsm2[tid] = 0.0f; }

    issueQhi(); stageQlo(); CP_COMMIT();
    CP_WAIT(0); __syncthreads();
    uint32_t Alr[4][4];
    #pragma unroll
    for (int kk = 0; kk < 4; kk++)
        ldsm4(Alr[kk][0], Alr[kk][1], Alr[kk][2], Alr[kk][3],
              smaddr(&Vs[(wm + afr) * KST + kk * 16 + afc]));
    __syncthreads();

    float rp0 = 0.f, rp1 = 0.f;

    if (WRITE_E) {
        // ====== pass 1: 1-mma rowsums (K-hi only), distance-2 prefetch ======
        __nv_bfloat16* kb[3] = { KB0, KB1, Vs };
        issueKhi(0, kb[0]); CP_COMMIT();
        issueKhi(1, kb[1]); CP_COMMIT();
        for (int kt = 0; kt < 16; kt++) {
            if (kt < 15) CP_WAIT(1); else CP_WAIT(0);
            __syncthreads();
            if (kt + 2 < 16) { issueKhi(kt + 2, kb[(kt + 2) % 3]); CP_COMMIT(); }
            const __nv_bfloat16* Kt = kb[kt % 3];
            float Sacc[8][4] = {};
            #pragma unroll
            for (int kk = 0; kk < 4; kk++) {
                uint32_t Ah[4];
                ldsm4(Ah[0], Ah[1], Ah[2], Ah[3],
                      smaddr(&Qs[(wm + afr) * QST + kk * 16 + afc]));
                #pragma unroll
                for (int g = 0; g < 4; g++) {
                    uint32_t Bh[4];
                    ldsm4(Bh[0], Bh[1], Bh[2], Bh[3],
                          smaddr(&Kt[(wn + g * 16 + bRow) * KST + kk * 16 + bc8]));
                    mma16816(Sacc[2 * g],     Ah, Bh[0], Bh[1]);
                    mma16816(Sacc[2 * g + 1], Ah, Bh[2], Bh[3]);
                }
            }
            #pragma unroll
            for (int nf = 0; nf < 8; nf++) {
                rp0 += __expf(Sacc[nf][0] * 0.125f) + __expf(Sacc[nf][1] * 0.125f);
                rp1 += __expf(Sacc[nf][2] * 0.125f) + __expf(Sacc[nf][3] * 0.125f);
            }
        }
        CP_WAIT(0);
        {
            float v0 = rp0, v1 = rp1;
            v0 += __shfl_xor_sync(0xffffffffu, v0, 1);
            v0 += __shfl_xor_sync(0xffffffffu, v0, 2);
            v1 += __shfl_xor_sync(0xffffffffu, v1, 1);
            v1 += __shfl_xor_sync(0xffffffffu, v1, 2);
            if ((l & 3) == 0) {
                atomicAdd(&rsm[wm + (l >> 2)], v0);
                atomicAdd(&rsm[wm + (l >> 2) + 8], v1);
            }
        }
        __syncthreads();
        if (tid < 64) rsm[tid] = 1.0f / rsm[tid];
        __syncthreads();
    }

    float inv0 = 1.0f, inv1 = 1.0f;
    if (WRITE_E) { inv0 = rsm[wm + (l >> 2)]; inv1 = rsm[wm + (l >> 2) + 8]; }
    rp0 = rp1 = 0.f;

    // ============ pass 2: full precision + PV ============
    float acc[8][4] = {};
    issueK(0, KB0); CP_COMMIT();
    for (int kt = 0; kt < 16; kt++) {
        CP_WAIT(0); __syncthreads();
        issueV(kt); CP_COMMIT();
        const __nv_bfloat16* Kt = (kt & 1) ? KB1 : KB0;

        float Sacc[8][4] = {};
        #pragma unroll
        for (int kk = 0; kk < 4; kk++) {
            uint32_t Ah[4];
            ldsm4(Ah[0], Ah[1], Ah[2], Ah[3],
                  smaddr(&Qs[(wm + afr) * QST + kk * 16 + afc]));
            #pragma unroll
            for (int g = 0; g < 4; g++) {
                uint32_t Bh[4], Bl[4];
                const int row = wn + g * 16 + bRow;
                ldsm4(Bh[0], Bh[1], Bh[2], Bh[3],
                      smaddr(&Kt[row * KST + kk * 16 + bc8]));
                ldsm4(Bl[0], Bl[1], Bl[2], Bl[3],
                      smaddr(&Kt[row * KST + 64 + kk * 16 + bc8]));
                #pragma unroll
                for (int sub = 0; sub < 2; sub++) {
                    float* c = Sacc[2 * g + sub];
                    mma16816(c, Ah,      Bh[2 * sub], Bh[2 * sub + 1]);
                    mma16816(c, Ah,      Bl[2 * sub], Bl[2 * sub + 1]);
                    mma16816(c, Alr[kk], Bh[2 * sub], Bh[2 * sub + 1]);
                }
            }
        }
        if (kt < 15) { issueK(kt + 1, (kt & 1) ? KB0 : KB1); CP_COMMIT(); }
        if (kt < 15) CP_WAIT(1); else CP_WAIT(0);
        __syncthreads();

        #pragma unroll
        for (int j = 0; j < 4; j++) {
            uint32_t Aph[4], Apl[4];
            #pragma unroll
            for (int t = 0; t < 2; t++) {
                float* c = Sacc[2 * j + t];
                float e0 = __expf(c[0] * 0.125f), e1 = __expf(c[1] * 0.125f);
                float e2 = __expf(c[2] * 0.125f), e3 = __expf(c[3] * 0.125f);
                if (WRITE_E) { e0 *= inv0; e1 *= inv0; e2 *= inv1; e3 *= inv1; }
                rp0 += e0 + e1; rp1 += e2 + e3;
                __nv_bfloat16 h0 = __float2bfloat16(e0), h1 = __float2bfloat16(e1);
                __nv_bfloat16 h2 = __float2bfloat16(e2), h3 = __float2bfloat16(e3);
                Aph[2 * t]     = packbf(__bfloat162float(h0), __bfloat162float(h1));
                Aph[2 * t + 1] = packbf(__bfloat162float(h2), __bfloat162float(h3));
                Apl[2 * t]     = packbf(e0 - __bfloat162float(h0), e1 - __bfloat162float(h1));
                Apl[2 * t + 1] = packbf(e2 - __bfloat162float(h2), e3 - __bfloat162float(h3));
                if (WRITE_E) {
                    const int grow = y0 + wm + (l >> 2);
                    const int gcol = kt * 128 + wn + (2 * j + t) * 8 + 2 * (l & 3);
                    *(float2*)&attn[((size_t)z * S + grow) * S + gcol] = make_float2(e0, e1);
                    *(float2*)&attn[((size_t)z * S + grow + 8) * S + gcol] = make_float2(e2, e3);
                }
            }
            #pragma unroll
            for (int g = 0; g < 4; g++) {
                uint32_t Vhf[4], Vlf[4];
                const int row = wn + j * 16 + vkr;
                ldsm4t(Vhf[0], Vhf[1], Vhf[2], Vhf[3],
                       smaddr(&Vs[row * KST + g * 16 + vnc]));
                ldsm4t(Vlf[0], Vlf[1], Vlf[2], Vlf[3],
                       smaddr(&Vs[row * KST + 64 + g * 16 + vnc]));
                #pragma unroll
                for (int sub = 0; sub < 2; sub++) {
                    float* c = acc[2 * g + sub];
                    mma16816(c, Aph, Vhf[2 * sub], Vhf[2 * sub + 1]);
                    mma16816(c, Aph, Vlf[2 * sub], Vlf[2 * sub + 1]);
                    mma16816(c, Apl, Vhf[2 * sub], Vhf[2 * sub + 1]);
                }
            }
        }
    }

    // ---- exact row sums of (pre-normalized) P -> rsm2 ----
    {
        float v0 = rp0, v1 = rp1;
        v0 += __shfl_xor_sync(0xffffffffu, v0, 1);
        v0 += __shfl_xor_sync(0xffffffffu, v0, 2);
        v1 += __shfl_xor_sync(0xffffffffu, v1, 1);
        v1 += __shfl_xor_sync(0xffffffffu, v1, 2);
        if ((l & 3) == 0) {
            atomicAdd(&rsm2[wm + (l >> 2)], v0);
            atomicAdd(&rsm2[wm + (l >> 2) + 8], v1);
        }
    }
    __syncthreads();
    if (tid < 64) rsm2[tid] = 1.0f / rsm2[tid];
    __syncthreads();

    // ---- pair-reduce ctx, exact scale, write as bf16 hi/lo planes ----
    const int er = l >> 2;
    if (w & 1) {
        #pragma unroll
        for (int nf = 0; nf < 8; nf++) {
            const int r = wm + er, c = nf * 8 + 2 * (l & 3);
            *(float2*)&rbuf[r * 66 + c] = make_float2(acc[nf][0], acc[nf][1]);
            *(float2*)&rbuf[(r + 8) * 66 + c] = make_float2(acc[nf][2], acc[nf][3]);
        }
    }
    __syncthreads();
    if (!(w & 1)) {
        const int r = wm + er;
        const float s0 = rsm2[r], s1 = rsm2[r + 8];
        #pragma unroll
        for (int nf = 0; nf < 8; nf++) {
            const int c = nf * 8 + 2 * (l & 3);
            float2 p0 = *(float2*)&rbuf[r * 66 + c];
            float2 p1 = *(float2*)&rbuf[(r + 8) * 66 + c];
            float o0 = (acc[nf][0] + p0.x) * s0, o1 = (acc[nf][1] + p0.y) * s0;
            float o2 = (acc[nf][2] + p1.x) * s1, o3 = (acc[nf][3] + p1.y) * s1;
            const size_t i0 = ((size_t)bz * S + y0 + r) * D + hz * 64 + c;
            const size_t i1 = ((size_t)bz * S + y0 + r + 8) * D + hz * 64 + c;
            __nv_bfloat16 h0 = __float2bfloat16(o0), h1 = __float2bfloat16(o1);
            __nv_bfloat16 h2 = __float2bfloat16(o2), h3 = __float2bfloat16(o3);
            *(uint32_t*)&cxh[i0] = packbf(__bfloat162float(h0), __bfloat162float(h1));
            *(uint32_t*)&cxl[i0] = packbf(o0 - __bfloat162float(h0),
                                          o1 - __bfloat162float(h1));
            *(uint32_t*)&cxh[i1] = packbf(__bfloat162float(h2), __bfloat162float(h3));
            *(uint32_t*)&cxl[i1] = packbf(o2 - __bfloat162float(h2),
                                          o3 - __bfloat162float(h3));
        }
    }
}

// ---------------------------------------------------------------------------
extern "C" void kernel_launch(void* const* d_in, const int* in_sizes, int n_in,
                              void* d_out, int out_size)
{
    const float* query = (const float*)d_in[0];
    const float* key_i = (const float*)d_in[1];
    const float* value = (const float*)d_in[2];
    const float* w_q   = (const float*)d_in[3];
    const float* w_k   = (const float*)d_in[4];
    const float* w_v   = (const float*)d_in[5];
    const float* w_o   = (const float*)d_in[6];
    float* out = (float*)d_out;

    __nv_bfloat16 *xqh, *xql, *xkh, *xkl, *xvh, *xvl;
    __nv_bfloat16 *wqh, *wql, *wkh, *wkl, *wvh, *wvl, *woh, *wol;
    __nv_bfloat16 *cxh, *cxl;
    __nv_bfloat16 *qh, *ql, *kh, *kl, *vh, *vl;
    cudaGetSymbolAddress((void**)&xqh, g_xqh); cudaGetSymbolAddress((void**)&xql, g_xql);
    cudaGetSymbolAddress((void**)&xkh, g_xkh); cudaGetSymbolAddress((void**)&xkl, g_xkl);
    cudaGetSymbolAddress((void**)&xvh, g_xvh); cudaGetSymbolAddress((void**)&xvl, g_xvl);
    cudaGetSymbolAddress((void**)&wqh, g_wqh); cudaGetSymbolAddress((void**)&wql, g_wql);
    cudaGetSymbolAddress((void**)&wkh, g_wkh); cudaGetSymbolAddress((void**)&wkl, g_wkl);
    cudaGetSymbolAddress((void**)&wvh, g_wvh); cudaGetSymbolAddress((void**)&wvl, g_wvl);
    cudaGetSymbolAddress((void**)&woh, g_woh); cudaGetSymbolAddress((void**)&wol, g_wol);
    cudaGetSymbolAddress((void**)&cxh, g_cxh); cudaGetSymbolAddress((void**)&cxl, g_cxl);
    cudaGetSymbolAddress((void**)&qh, g_qh);   cudaGetSymbolAddress((void**)&ql, g_ql);
    cudaGetSymbolAddress((void**)&kh, g_kh);   cudaGetSymbolAddress((void**)&kl, g_kl);
    cudaGetSymbolAddress((void**)&vh, g_vh);   cudaGetSymbolAddress((void**)&vl, g_vl);

    const bool want_attn = ((long long)out_size >= OUT_ELEMS + ATT_ELEMS);
    float* attn = want_attn ? (out + OUT_ELEMS) : nullptr;

    // ---- 1. split fp32 inputs/weights into bf16 hi/lo planes ----
    ConvArgs ca{};
    ca.src[0] = query; ca.hi[0] = xqh; ca.lo[0] = xql; ca.n4[0] = (int)(OUT_ELEMS / 4);
    ca.src[1] = key_i; ca.hi[1] = xkh; ca.lo[1] = xkl; ca.n4[1] = (int)(OUT_ELEMS / 4);
    ca.src[2] = value; ca.hi[2] = xvh; ca.lo[2] = xvl; ca.n4[2] = (int)(OUT_ELEMS / 4);
    ca.src[3] = w_q;   ca.hi[3] = wqh; ca.lo[3] = wql; ca.n4[3] = D * D / 4;
    ca.src[4] = w_k;   ca.hi[4] = wkh; ca.lo[4] = wkl; ca.n4[4] = D * D / 4;
    ca.src[5] = w_v;   ca.hi[5] = wvh; ca.lo[5] = wvl; ca.n4[5] = D * D / 4;
    ca.src[6] = w_o;   ca.hi[6] = woh; ca.lo[6] = wol; ca.n4[6] = D * D / 4;
    convert_split<<<dim3((unsigned)(OUT_ELEMS / 4 / 256), 1, 7), 256>>>(ca);

    cudaFuncSetAttribute(gemm_bf16<1>, cudaFuncAttributeMaxDynamicSharedMemorySize, GSMEM);
    cudaFuncSetAttribute(gemm_bf16<0>, cudaFuncAttributeMaxDynamicSharedMemorySize, GSMEM);

    // ---- 2. q/k/v projections (one launch, grid.z=3) ----
    GemmArgs gp{};
    gp.ah[0] = xqh; gp.al[0] = xql; gp.bh[0] = wqh; gp.bl[0] = wql;
    gp.ah[1] = xkh; gp.al[1] = xkl; gp.bh[1] = wkh; gp.bl[1] = wkl;
    gp.ah[2] = xvh; gp.al[2] = xvl; gp.bh[2] = wvh; gp.bl[2] = wvl;
    gp.chi[0] = qh; gp.clo[0] = ql;
    gp.chi[1] = kh; gp.clo[1] = kl;
    gp.chi[2] = vh; gp.clo[2] = vl;
    gemm_bf16<1><<<dim3(8, 32, 3), 256, GSMEM>>>(gp);

    // ---- 3. fused attention (ctx written directly as hi/lo planes) ----
    const int smem = (64 * QST + 3 * 128 * KST) * 2 + 128 * 4;   // 114176 B
    const dim3 gf(S / 64, BH);
    if (want_attn) {
        cudaFuncSetAttribute(fused_attn<true>,
                             cudaFuncAttributeMaxDynamicSharedMemorySize, smem);
        fused_attn<true><<<gf, dim3(256), smem>>>(qh, ql, kh, kl, vh, vl, cxh, cxl, attn);
    } else {
        cudaFuncSetAttribute(fused_attn<false>,
                             cudaFuncAttributeMaxDynamicSharedMemorySize, smem);
        fused_attn<false><<<gf, dim3(256), smem>>>(qh, ql, kh, kl, vh, vl, cxh, cxl, nullptr);
    }

    // ---- 4. out = ctx @ Wo^T ----
    GemmArgs go{};
    go.ah[0] = cxh; go.al[0] = cxl; go.bh[0] = woh; go.bl[0] = wol;
    go.c = out;
    gemm_bf16<0><<<dim3(8, 32, 1), 256, GSMEM>>>(go);
}